// round 2
// baseline (speedup 1.0000x reference)
#include <cuda_runtime.h>
#include <cuda_bf16.h>
#include <cstdint>

// DeltaNet chunkwise delta-rule linear attention with decay.
// b=4 h=4 (BH=16), L=4096, dk=dv=256, chunk C=32, NCH=128 chunks.
//
//  pre_kernel  : per-chunk parallel precompute (norms, T via forward subst, u_raw, w, attn, gamma-mean)
//  scan_kernel : ONE persistent launch. 128 CTAs (16 bh x 8 v-blocks), 256 thr.
//                S slice resident in smem; cp.async double-buffered operand prefetch;
//                all GEMM-lets use packed fma.rn.f32x2 (FFMA2).

#define BHn 16
#define LSEQ 4096
#define DK 256
#define DV 256
#define CC 32
#define NCH 128
#define CHELEM (CC*DK)          // 8192 floats per chunk per tensor

// -------- scratch (device globals; no allocation allowed) --------
__device__ float g_qT[BHn*NCH*CHELEM];     // [bh][ch][k][c]  (k-major)
__device__ float g_kn[BHn*NCH*CHELEM];     // [bh][ch][c][k]  (c-major)
__device__ float g_wT[BHn*NCH*CHELEM];     // [bh][ch][k][c]
__device__ float g_u [BHn*NCH*CHELEM];     // [bh][ch][c][v]  (u_raw)
__device__ float g_attnT[BHn*NCH*CC*CC];   // [bh][ch][d][c] = attn[c][d] (masked d<=c)
__device__ float g_gm[BHn*NCH];

// ---------- packed f32x2 helpers ----------
typedef unsigned long long ull;

__device__ __forceinline__ void ffma2(ull &d, ull a, ull b) {
    asm("fma.rn.f32x2 %0, %1, %2, %0;" : "+l"(d) : "l"(a), "l"(b));
}
__device__ __forceinline__ ull pk2(float a, float b) {
    ull r; asm("mov.b64 %0, {%1, %2};" : "=l"(r) : "f"(a), "f"(b)); return r;
}
__device__ __forceinline__ float2 up2(ull p) {
    float2 r; asm("mov.b64 {%0, %1}, %2;" : "=f"(r.x), "=f"(r.y) : "l"(p)); return r;
}
__device__ __forceinline__ uint32_t smem_u32(const void* p) {
    uint32_t a;
    asm("{ .reg .u64 t; cvta.to.shared.u64 t, %1; cvt.u32.u64 %0, t; }" : "=r"(a) : "l"(p));
    return a;
}
__device__ __forceinline__ void cpa16(uint32_t dst, const void* src) {
    asm volatile("cp.async.cg.shared.global [%0], [%1], 16;" :: "r"(dst), "l"(src));
}
#define CP_COMMIT() asm volatile("cp.async.commit_group;")
#define CP_WAIT0()  asm volatile("cp.async.wait_group 0;")
#define CP_WAIT1()  asm volatile("cp.async.wait_group 1;")

// ================= preprocess =================
#define PRE_SMEM_FLOATS (8320+8320+1056+32+32)

__global__ void pre_kernel(const float* __restrict__ q, const float* __restrict__ k,
                           const float* __restrict__ v, const float* __restrict__ beta,
                           const float* __restrict__ gamma) {
    extern __shared__ float sm[];
    float* qs = sm;              // 32*260
    float* ks = sm + 8320;       // 32*260
    float* As = sm + 16640;      // 32*33
    float* bs = sm + 17696;      // 32
    float* gs = sm + 17728;      // 32

    const int tid  = threadIdx.x;
    const int lane = tid & 31;
    const int wid  = tid >> 5;
    const int bh = blockIdx.x >> 7;
    const int ch = blockIdx.x & 127;
    const long tok0 = (long)bh*LSEQ + (long)ch*CC;

    const float* qg = q + tok0*DK;
    const float* kg = k + tok0*DK;

    #pragma unroll 8
    for (int i = 0; i < 32; i++) {
        qs[i*260 + tid] = qg[i*DK + tid];
        ks[i*260 + tid] = kg[i*DK + tid];
    }
    if (tid < 32) { bs[tid] = beta[tok0 + tid]; gs[tid] = gamma[tok0 + tid]; }
    __syncthreads();

    // l2 normalize rows (warp per row)
    for (int r = wid; r < 32; r += 8) {
        float s = 0.f;
        #pragma unroll
        for (int x = lane; x < 256; x += 32) { float t = qs[r*260+x]; s += t*t; }
        s += __shfl_xor_sync(0xffffffffu, s, 16);
        s += __shfl_xor_sync(0xffffffffu, s, 8);
        s += __shfl_xor_sync(0xffffffffu, s, 4);
        s += __shfl_xor_sync(0xffffffffu, s, 2);
        s += __shfl_xor_sync(0xffffffffu, s, 1);
        float inv = rsqrtf(s + 1e-6f);
        #pragma unroll
        for (int x = lane; x < 256; x += 32) qs[r*260+x] *= inv;

        float s2 = 0.f;
        #pragma unroll
        for (int x = lane; x < 256; x += 32) { float t = ks[r*260+x]; s2 += t*t; }
        s2 += __shfl_xor_sync(0xffffffffu, s2, 16);
        s2 += __shfl_xor_sync(0xffffffffu, s2, 8);
        s2 += __shfl_xor_sync(0xffffffffu, s2, 4);
        s2 += __shfl_xor_sync(0xffffffffu, s2, 2);
        s2 += __shfl_xor_sync(0xffffffffu, s2, 1);
        float inv2 = rsqrtf(s2 + 1e-6f);
        #pragma unroll
        for (int x = lane; x < 256; x += 32) ks[r*260+x] *= inv2;
    }
    __syncthreads();

    const long cb = ((long)bh*NCH + ch)*CHELEM;

    // write kn (c-major) and qT (k-major)
    {
        float* knp = g_kn + cb;
        #pragma unroll 8
        for (int i = 0; i < 32; i++) knp[i*DK + tid] = ks[i*260 + tid];
        #pragma unroll
        for (int g2 = 0; g2 < 8; g2++) {
            float4 t4 = make_float4(qs[(g2*4+0)*260+tid], qs[(g2*4+1)*260+tid],
                                    qs[(g2*4+2)*260+tid], qs[(g2*4+3)*260+tid]);
            *(float4*)&g_qT[cb + (long)tid*32 + g2*4] = t4;
        }
    }

    // A = -beta_i*(kn_i.kn_j) (j<i) ; attnT[j][i] = (j<=i)? qn_i.kn_j : 0
    {
        float* atp = g_attnT + ((long)bh*NCH + ch)*CC*CC;
        #pragma unroll
        for (int p = 0; p < 4; p++) {
            int j = p*8 + wid;
            int i = lane;
            float accA = 0.f, accQ = 0.f;
            #pragma unroll 8
            for (int k4 = 0; k4 < 64; k4++) {
                float4 kj = *(float4*)&ks[j*260 + k4*4];
                float4 ki = *(float4*)&ks[i*260 + k4*4];
                float4 qi = *(float4*)&qs[i*260 + k4*4];
                accA += ki.x*kj.x + ki.y*kj.y + ki.z*kj.z + ki.w*kj.w;
                accQ += qi.x*kj.x + qi.y*kj.y + qi.z*kj.z + qi.w*kj.w;
            }
            if (j < i) As[i*33 + j] = -bs[i]*accA;
            atp[j*32 + i] = (j <= i) ? accQ : 0.0f;
        }
    }
    __syncthreads();

    // forward substitution (warp 0): strict-lower T in As
    if (wid == 0) {
        int col = lane;
        for (int i = 1; i < 32; i++) {
            float inc = 0.f;
            if (col < i) {
                for (int j = col+1; j < i; j++) inc += As[i*33+j]*As[j*33+col];
            }
            __syncwarp();
            if (col < i) As[i*33+col] += inc;
            __syncwarp();
        }
    }
    if (wid == 1) {
        float g2 = gs[lane];
        g2 += __shfl_xor_sync(0xffffffffu, g2, 16);
        g2 += __shfl_xor_sync(0xffffffffu, g2, 8);
        g2 += __shfl_xor_sync(0xffffffffu, g2, 4);
        g2 += __shfl_xor_sync(0xffffffffu, g2, 2);
        g2 += __shfl_xor_sync(0xffffffffu, g2, 1);
        if (lane == 0) g_gm[bh*NCH + ch] = g2 * (1.0f/32.0f);
    }
    __syncthreads();

    // u_raw = T (beta*v)
    {
        float colv[32];
        const float* vg = v + tok0*DV;
        #pragma unroll
        for (int j = 0; j < 32; j++) colv[j] = vg[j*DV + tid] * bs[j];
        float* up = g_u + cb;
        #pragma unroll
        for (int i = 0; i < 32; i++) {
            float acc = colv[i];
            #pragma unroll
            for (int j = 0; j < i; j++) acc += As[i*33+j]*colv[j];
            up[i*DV + tid] = acc;
        }
    }
    // w = T (beta*kn), k-major
    {
        float colk[32];
        #pragma unroll
        for (int j = 0; j < 32; j++) colk[j] = ks[j*260 + tid] * bs[j];
        float wout[32];
        #pragma unroll
        for (int i = 0; i < 32; i++) {
            float acc = colk[i];
            #pragma unroll
            for (int j = 0; j < i; j++) acc += As[i*33+j]*colk[j];
            wout[i] = acc;
        }
        #pragma unroll
        for (int g2 = 0; g2 < 8; g2++)
            *(float4*)&g_wT[cb + (long)tid*32 + g2*4] =
                make_float4(wout[g2*4], wout[g2*4+1], wout[g2*4+2], wout[g2*4+3]);
    }
}

// ================= persistent scan =================
// smem float layout:
//  S   [256][36]          0      (9216)
//  W0  [256][32]          9216
//  Q0  [256][32]          17408
//  W1  [256][32]          25600
//  Q1  [256][32]          33792
//  U0  [32][36]           41984
//  U1  [32][36]           43136
//  A0  [32][36]           44288
//  A1  [32][36]           45440
//  K   [32][256]          46592  (8192)
//  US  [32][36]           54784
#define OFF_S   0
#define OFF_W0  9216
#define OFF_Q0  17408
#define OFF_W1  25600
#define OFF_Q1  33792
#define OFF_U0  41984
#define OFF_U1  43136
#define OFF_A0  44288
#define OFF_A1  45440
#define OFF_K   46592
#define OFF_US  54784
#define SCAN_SMEM_FLOATS 55936   // 223744 bytes

__global__ __launch_bounds__(256, 1)
void scan_kernel(float* __restrict__ outp, float* __restrict__ sFinal) {
    extern __shared__ float sm[];
    const uint32_t smb = smem_u32(sm);

    const int tid  = threadIdx.x;
    const int lane = tid & 31;
    const int wid  = tid >> 5;
    const int bh = blockIdx.y;
    const int v0 = blockIdx.x * 32;

    float* Ss = sm + OFF_S;
    float* us = sm + OFF_US;
    float* kb = sm + OFF_K;

    const long bhoff = (long)bh*NCH*CHELEM;

    // zero resident S slice
    #pragma unroll
    for (int i = 0; i < 36; i++) Ss[tid + i*256] = 0.0f;

    // helper lambdas for prefetch (as macros to keep addresses simple)
    // G(group for chunk tn into buffer tn&1): wT, qT, u-slice, attn
    {
        const int tn = 0, bsel = 0;
        const long cb = bhoff + (long)tn*CHELEM;
        const float4* wsrc = (const float4*)(g_wT + cb);
        const float4* qsrc = (const float4*)(g_qT + cb);
        uint32_t wdst = smb + (OFF_W0 + bsel*16384)*4;
        uint32_t qdst = smb + (OFF_Q0 + bsel*16384)*4;
        #pragma unroll
        for (int it = 0; it < 8; it++) {
            int idx = tid + it*256;
            cpa16(wdst + idx*16, wsrc + idx);
            cpa16(qdst + idx*16, qsrc + idx);
        }
        const float* usrc = g_u + cb + (tid>>3)*DV + v0 + (tid&7)*4;
        uint32_t udst = smb + (OFF_U0 + bsel*1152 + (tid>>3)*36 + (tid&7)*4)*4;
        cpa16(udst, usrc);
        const float* asrc = g_attnT + ((long)bh*NCH + tn)*CC*CC + tid*4;
        uint32_t adst = smb + (OFF_A0 + bsel*1152 + (tid>>3)*36 + (tid&7)*4)*4;
        cpa16(adst, asrc);
        CP_COMMIT();
    }

    for (int t = 0; t < NCH; t++) {
        CP_WAIT0();
        __syncthreads();   // chunk-t operands visible; S(t-1) update visible

        const long cb = bhoff + (long)t*CHELEM;
        const int bsel = t & 1;

        // ---- issue kn(t) prefetch ----
        {
            const float4* ksrc = (const float4*)(g_kn + cb);
            uint32_t kdst = smb + OFF_K*4;
            #pragma unroll
            for (int it = 0; it < 8; it++) {
                int idx = tid + it*256;
                cpa16(kdst + idx*16, ksrc + idx);
            }
            CP_COMMIT();
        }
        // ---- issue G(t+1) prefetch ----
        if (t + 1 < NCH) {
            const int tn = t + 1, nb = tn & 1;
            const long cbn = bhoff + (long)tn*CHELEM;
            const float4* wsrc = (const float4*)(g_wT + cbn);
            const float4* qsrc = (const float4*)(g_qT + cbn);
            uint32_t wdst = smb + (OFF_W0 + nb*16384)*4;
            uint32_t qdst = smb + (OFF_Q0 + nb*16384)*4;
            #pragma unroll
            for (int it = 0; it < 8; it++) {
                int idx = tid + it*256;
                cpa16(wdst + idx*16, wsrc + idx);
                cpa16(qdst + idx*16, qsrc + idx);
            }
            const float* usrc = g_u + cbn + (tid>>3)*DV + v0 + (tid&7)*4;
            uint32_t udst = smb + (OFF_U0 + nb*1152 + (tid>>3)*36 + (tid&7)*4)*4;
            cpa16(udst, usrc);
            const float* asrc = g_attnT + ((long)bh*NCH + tn)*CC*CC + tid*4;
            uint32_t adst = smb + (OFF_A0 + nb*1152 + (tid>>3)*36 + (tid&7)*4)*4;
            cpa16(adst, asrc);
            CP_COMMIT();
        }

        const float* wb = sm + OFF_W0 + bsel*16384;
        const float* qb = sm + OFF_Q0 + bsel*16384;
        const float* ub = sm + OFF_U0 + bsel*1152;
        const float* ab = sm + OFF_A0 + bsel*1152;

        // ---- phase 1: u = w.S, o = q.S  (rows c=4*wid..+3, col v=lane), f32x2 ----
        ull U01 = 0, U23 = 0, O01 = 0, O23 = 0;
        {
            const int cbase = wid*4;
            #pragma unroll 4
            for (int k = 0; k < 256; k++) {
                float s = Ss[k*36 + lane];
                ull ss = pk2(s, s);
                ulonglong2 w2 = *(const ulonglong2*)&wb[k*32 + cbase];
                ulonglong2 q2 = *(const ulonglong2*)&qb[k*32 + cbase];
                ffma2(U01, w2.x, ss);
                ffma2(U23, w2.y, ss);
                ffma2(O01, q2.x, ss);
                ffma2(O23, q2.y, ss);
            }
        }
        // tail: us = u_raw - w.S
        {
            const int c = wid*4;
            float2 u01 = up2(U01), u23 = up2(U23);
            us[(c+0)*36 + lane] = ub[(c+0)*36 + lane] - u01.x;
            us[(c+1)*36 + lane] = ub[(c+1)*36 + lane] - u01.y;
            us[(c+2)*36 + lane] = ub[(c+2)*36 + lane] - u23.x;
            us[(c+3)*36 + lane] = ub[(c+3)*36 + lane] - u23.y;
        }

        // wait for kn(t) (G(t+1) may still be pending)
        if (t + 1 < NCH) { CP_WAIT1(); } else { CP_WAIT0(); }
        __syncthreads();

        // ---- phase 2: o += attn_local . u ----
        {
            const int cbase = wid*4;
            #pragma unroll 4
            for (int d = 0; d < 32; d++) {
                float uu = us[d*36 + lane];
                ull uup = pk2(uu, uu);
                ulonglong2 a2 = *(const ulonglong2*)&ab[d*36 + cbase];
                ffma2(O01, a2.x, uup);
                ffma2(O23, a2.y, uup);
            }
            float* op = outp + ((long)bh*LSEQ + (long)t*CC)*DV;
            const int c = wid*4;
            float2 o01 = up2(O01), o23 = up2(O23);
            op[(c+0)*DV + v0 + lane] = o01.x;
            op[(c+1)*DV + v0 + lane] = o01.y;
            op[(c+2)*DV + v0 + lane] = o23.x;
            op[(c+3)*DV + v0 + lane] = o23.y;
        }

        // ---- phase 3: S = gm*S + kn^T.u  (lane = k offset, warp = v group of 4) ----
        {
            const int kx = lane, vy = wid;
            ull accP[16];
            #pragma unroll
            for (int z = 0; z < 16; z++) accP[z] = 0ull;
            #pragma unroll 2
            for (int c = 0; c < 32; c++) {
                ulonglong2 u2 = *(const ulonglong2*)&us[c*36 + vy*4];
                const float* kr = &kb[c*DK + kx];
                #pragma unroll
                for (int kg = 0; kg < 8; kg++) {
                    float kv = kr[kg*32];
                    ull kvp = pk2(kv, kv);
                    ffma2(accP[kg*2+0], kvp, u2.x);
                    ffma2(accP[kg*2+1], kvp, u2.y);
                }
            }
            const float gm = g_gm[bh*NCH + t];
            const ull gmp = pk2(gm, gm);
            const bool last = (t == NCH-1);
            float* sfp = sFinal + (long)bh*DK*DV;
            #pragma unroll
            for (int kg = 0; kg < 8; kg++) {
                int k = kg*32 + kx;
                ulonglong2 so = *(const ulonglong2*)&Ss[k*36 + vy*4];
                ull n0 = accP[kg*2+0], n1 = accP[kg*2+1];
                ffma2(n0, so.x, gmp);
                ffma2(n1, so.y, gmp);
                ulonglong2 sn; sn.x = n0; sn.y = n1;
                *(ulonglong2*)&Ss[k*36 + vy*4] = sn;
                if (last) *(ulonglong2*)&sfp[(long)k*DV + v0 + vy*4] = sn;
            }
        }
        // loop top's __syncthreads orders phase-3 S writes vs next phase 1
    }
}

// ================= launch =================
extern "C" void kernel_launch(void* const* d_in, const int* in_sizes, int n_in,
                              void* d_out, int out_size) {
    const float* q     = (const float*)d_in[0];
    const float* k     = (const float*)d_in[1];
    const float* v     = (const float*)d_in[2];
    const float* beta  = (const float*)d_in[3];
    const float* gamma = (const float*)d_in[4];
    float* outp = (float*)d_out;
    float* sfin = outp + (long)BHn*LSEQ*DV;   // S appended after out

    cudaFuncSetAttribute(pre_kernel,  cudaFuncAttributeMaxDynamicSharedMemorySize,
                         PRE_SMEM_FLOATS*4);
    cudaFuncSetAttribute(scan_kernel, cudaFuncAttributeMaxDynamicSharedMemorySize,
                         SCAN_SMEM_FLOATS*4);
    (void)in_sizes; (void)n_in; (void)out_size;

    pre_kernel<<<BHn*NCH, 256, PRE_SMEM_FLOATS*4>>>(q, k, v, beta, gamma);
    scan_kernel<<<dim3(8, BHn), 256, SCAN_SMEM_FLOATS*4>>>(outp, sfin);
}

// round 3
// speedup vs baseline: 1.5751x; 1.5751x over previous
#include <cuda_runtime.h>
#include <cuda_bf16.h>
#include <cstdint>

// DeltaNet chunkwise delta-rule linear attention with decay.
// b=4 h=4 (BH=16), L=4096, dk=dv=256, chunk C=32, NCH=128 chunks.
//
//  pre_kernel  : per-chunk parallel precompute (norms, T via forward subst, u_raw, w, attn, gamma-mean)
//  scan_kernel : ONE persistent launch. 128 CTAs (16 bh x 8 v-blocks), 512 thr (16 warps).
//                S slice resident in smem; cp.async double-buffered operand prefetch;
//                k-split / c-split phases so 4 warps/SMSP hide LDS+FMA latency.

#define BHn 16
#define LSEQ 4096
#define DK 256
#define DV 256
#define CC 32
#define NCH 128
#define CHELEM (CC*DK)          // 8192 floats per chunk per tensor

// -------- scratch (device globals; no allocation allowed) --------
__device__ float g_qT[BHn*NCH*CHELEM];     // [bh][ch][k][c]  (k-major)
__device__ float g_kn[BHn*NCH*CHELEM];     // [bh][ch][c][k]  (c-major)
__device__ float g_wT[BHn*NCH*CHELEM];     // [bh][ch][k][c]
__device__ float g_u [BHn*NCH*CHELEM];     // [bh][ch][c][v]  (u_raw)
__device__ float g_attnT[BHn*NCH*CC*CC];   // [bh][ch][d][c] = attn[c][d] (masked d<=c)
__device__ float g_gm[BHn*NCH];

// ---------- packed f32x2 helpers ----------
typedef unsigned long long ull;

__device__ __forceinline__ void ffma2(ull &d, ull a, ull b) {
    asm("fma.rn.f32x2 %0, %1, %2, %0;" : "+l"(d) : "l"(a), "l"(b));
}
__device__ __forceinline__ ull pk2(float a, float b) {
    ull r; asm("mov.b64 %0, {%1, %2};" : "=l"(r) : "f"(a), "f"(b)); return r;
}
__device__ __forceinline__ float2 up2(ull p) {
    float2 r; asm("mov.b64 {%0, %1}, %2;" : "=f"(r.x), "=f"(r.y) : "l"(p)); return r;
}
__device__ __forceinline__ uint32_t smem_u32(const void* p) {
    uint32_t a;
    asm("{ .reg .u64 t; cvta.to.shared.u64 t, %1; cvt.u32.u64 %0, t; }" : "=r"(a) : "l"(p));
    return a;
}
__device__ __forceinline__ void cpa16(uint32_t dst, const void* src) {
    asm volatile("cp.async.cg.shared.global [%0], [%1], 16;" :: "r"(dst), "l"(src));
}
#define CP_COMMIT() asm volatile("cp.async.commit_group;")
#define CP_WAIT0()  asm volatile("cp.async.wait_group 0;")
#define CP_WAIT1()  asm volatile("cp.async.wait_group 1;")

// ================= preprocess =================
#define PRE_SMEM_FLOATS (8320+8320+1056+32+32)

__global__ void pre_kernel(const float* __restrict__ q, const float* __restrict__ k,
                           const float* __restrict__ v, const float* __restrict__ beta,
                           const float* __restrict__ gamma) {
    extern __shared__ float sm[];
    float* qs = sm;              // 32*260
    float* ks = sm + 8320;       // 32*260
    float* As = sm + 16640;      // 32*33
    float* bs = sm + 17696;      // 32
    float* gs = sm + 17728;      // 32

    const int tid  = threadIdx.x;
    const int lane = tid & 31;
    const int wid  = tid >> 5;
    const int bh = blockIdx.x >> 7;
    const int ch = blockIdx.x & 127;
    const long tok0 = (long)bh*LSEQ + (long)ch*CC;

    const float* qg = q + tok0*DK;
    const float* kg = k + tok0*DK;

    #pragma unroll 8
    for (int i = 0; i < 32; i++) {
        qs[i*260 + tid] = qg[i*DK + tid];
        ks[i*260 + tid] = kg[i*DK + tid];
    }
    if (tid < 32) { bs[tid] = beta[tok0 + tid]; gs[tid] = gamma[tok0 + tid]; }
    __syncthreads();

    // l2 normalize rows (warp per row)
    for (int r = wid; r < 32; r += 8) {
        float s = 0.f;
        #pragma unroll
        for (int x = lane; x < 256; x += 32) { float t = qs[r*260+x]; s += t*t; }
        s += __shfl_xor_sync(0xffffffffu, s, 16);
        s += __shfl_xor_sync(0xffffffffu, s, 8);
        s += __shfl_xor_sync(0xffffffffu, s, 4);
        s += __shfl_xor_sync(0xffffffffu, s, 2);
        s += __shfl_xor_sync(0xffffffffu, s, 1);
        float inv = rsqrtf(s + 1e-6f);
        #pragma unroll
        for (int x = lane; x < 256; x += 32) qs[r*260+x] *= inv;

        float s2 = 0.f;
        #pragma unroll
        for (int x = lane; x < 256; x += 32) { float t = ks[r*260+x]; s2 += t*t; }
        s2 += __shfl_xor_sync(0xffffffffu, s2, 16);
        s2 += __shfl_xor_sync(0xffffffffu, s2, 8);
        s2 += __shfl_xor_sync(0xffffffffu, s2, 4);
        s2 += __shfl_xor_sync(0xffffffffu, s2, 2);
        s2 += __shfl_xor_sync(0xffffffffu, s2, 1);
        float inv2 = rsqrtf(s2 + 1e-6f);
        #pragma unroll
        for (int x = lane; x < 256; x += 32) ks[r*260+x] *= inv2;
    }
    __syncthreads();

    const long cb = ((long)bh*NCH + ch)*CHELEM;

    // write kn (c-major) and qT (k-major)
    {
        float* knp = g_kn + cb;
        #pragma unroll 8
        for (int i = 0; i < 32; i++) knp[i*DK + tid] = ks[i*260 + tid];
        #pragma unroll
        for (int g2 = 0; g2 < 8; g2++) {
            float4 t4 = make_float4(qs[(g2*4+0)*260+tid], qs[(g2*4+1)*260+tid],
                                    qs[(g2*4+2)*260+tid], qs[(g2*4+3)*260+tid]);
            *(float4*)&g_qT[cb + (long)tid*32 + g2*4] = t4;
        }
    }

    // A = -beta_i*(kn_i.kn_j) (j<i) ; attnT[j][i] = (j<=i)? qn_i.kn_j : 0
    {
        float* atp = g_attnT + ((long)bh*NCH + ch)*CC*CC;
        #pragma unroll
        for (int p = 0; p < 4; p++) {
            int j = p*8 + wid;
            int i = lane;
            float accA = 0.f, accQ = 0.f;
            #pragma unroll 8
            for (int k4 = 0; k4 < 64; k4++) {
                float4 kj = *(float4*)&ks[j*260 + k4*4];
                float4 ki = *(float4*)&ks[i*260 + k4*4];
                float4 qi = *(float4*)&qs[i*260 + k4*4];
                accA += ki.x*kj.x + ki.y*kj.y + ki.z*kj.z + ki.w*kj.w;
                accQ += qi.x*kj.x + qi.y*kj.y + qi.z*kj.z + qi.w*kj.w;
            }
            if (j < i) As[i*33 + j] = -bs[i]*accA;
            atp[j*32 + i] = (j <= i) ? accQ : 0.0f;
        }
    }
    __syncthreads();

    // forward substitution (warp 0): strict-lower T in As
    if (wid == 0) {
        int col = lane;
        for (int i = 1; i < 32; i++) {
            float inc = 0.f;
            if (col < i) {
                for (int j = col+1; j < i; j++) inc += As[i*33+j]*As[j*33+col];
            }
            __syncwarp();
            if (col < i) As[i*33+col] += inc;
            __syncwarp();
        }
    }
    if (wid == 1) {
        float g2 = gs[lane];
        g2 += __shfl_xor_sync(0xffffffffu, g2, 16);
        g2 += __shfl_xor_sync(0xffffffffu, g2, 8);
        g2 += __shfl_xor_sync(0xffffffffu, g2, 4);
        g2 += __shfl_xor_sync(0xffffffffu, g2, 2);
        g2 += __shfl_xor_sync(0xffffffffu, g2, 1);
        if (lane == 0) g_gm[bh*NCH + ch] = g2 * (1.0f/32.0f);
    }
    __syncthreads();

    // u_raw = T (beta*v)
    {
        float colv[32];
        const float* vg = v + tok0*DV;
        #pragma unroll
        for (int j = 0; j < 32; j++) colv[j] = vg[j*DV + tid] * bs[j];
        float* up = g_u + cb;
        #pragma unroll
        for (int i = 0; i < 32; i++) {
            float acc = colv[i];
            #pragma unroll
            for (int j = 0; j < i; j++) acc += As[i*33+j]*colv[j];
            up[i*DV + tid] = acc;
        }
    }
    // w = T (beta*kn), k-major
    {
        float colk[32];
        #pragma unroll
        for (int j = 0; j < 32; j++) colk[j] = ks[j*260 + tid] * bs[j];
        float wout[32];
        #pragma unroll
        for (int i = 0; i < 32; i++) {
            float acc = colk[i];
            #pragma unroll
            for (int j = 0; j < i; j++) acc += As[i*33+j]*colk[j];
            wout[i] = acc;
        }
        #pragma unroll
        for (int g2 = 0; g2 < 8; g2++)
            *(float4*)&g_wT[cb + (long)tid*32 + g2*4] =
                make_float4(wout[g2*4], wout[g2*4+1], wout[g2*4+2], wout[g2*4+3]);
    }
}

// ================= persistent scan (512 threads) =================
// smem float layout:
#define OFF_S   0        // [256][36]
#define OFF_W0  9216     // [256][32]
#define OFF_Q0  17408
#define OFF_W1  25600
#define OFF_Q1  33792
#define OFF_U0  41984    // [32][36]
#define OFF_U1  43136
#define OFF_A0  44288    // [32][36]
#define OFF_A1  45440
#define OFF_K   46592    // [32][256]
#define OFF_US  54784    // [32][36] final u (also partial-B buffer)
#define OFF_PO  55936    // [32][36] combined o
#define SCAN_SMEM_FLOATS 57088   // 228352 bytes

__global__ __launch_bounds__(512, 1)
void scan_kernel(float* __restrict__ outp, float* __restrict__ sFinal) {
    extern __shared__ float sm[];
    const uint32_t smb = smem_u32(sm);

    const int tid  = threadIdx.x;
    const int lane = tid & 31;
    const int wid  = tid >> 5;          // 0..15
    const int bh = blockIdx.y;
    const int v0 = blockIdx.x * 32;

    float* Ss = sm + OFF_S;
    float* us = sm + OFF_US;
    float* po = sm + OFF_PO;
    float* kb = sm + OFF_K;

    const long bhoff = (long)bh*NCH*CHELEM;

    // zero resident S slice (9216 floats)
    #pragma unroll
    for (int i = 0; i < 18; i++) Ss[tid + i*512] = 0.0f;

    // prefetch G(0): wT, qT, u-slice, attn
    {
        const long cb = bhoff;
        const float4* wsrc = (const float4*)(g_wT + cb);
        const float4* qsrc = (const float4*)(g_qT + cb);
        uint32_t wdst = smb + OFF_W0*4;
        uint32_t qdst = smb + OFF_Q0*4;
        #pragma unroll
        for (int it = 0; it < 4; it++) {
            int idx = tid + it*512;
            cpa16(wdst + idx*16, wsrc + idx);
            cpa16(qdst + idx*16, qsrc + idx);
        }
        if (tid < 256) {
            const float* usrc = g_u + cb + (tid>>3)*DV + v0 + (tid&7)*4;
            uint32_t udst = smb + (OFF_U0 + (tid>>3)*36 + (tid&7)*4)*4;
            cpa16(udst, usrc);
            const float* asrc = g_attnT + (long)bh*NCH*CC*CC + tid*4;
            uint32_t adst = smb + (OFF_A0 + (tid>>3)*36 + (tid&7)*4)*4;
            cpa16(adst, asrc);
        }
        CP_COMMIT();
    }

    for (int t = 0; t < NCH; t++) {
        CP_WAIT0();
        __syncthreads();   // chunk-t operands visible; S(t-1) update visible

        const long cb = bhoff + (long)t*CHELEM;
        const int bsel = t & 1;

        // ---- issue kn(t) prefetch ----
        {
            const float4* ksrc = (const float4*)(g_kn + cb);
            uint32_t kdst = smb + OFF_K*4;
            #pragma unroll
            for (int it = 0; it < 4; it++) {
                int idx = tid + it*512;
                cpa16(kdst + idx*16, ksrc + idx);
            }
            CP_COMMIT();
        }
        // ---- issue G(t+1) prefetch ----
        if (t + 1 < NCH) {
            const int tn = t + 1, nb = tn & 1;
            const long cbn = bhoff + (long)tn*CHELEM;
            const float4* wsrc = (const float4*)(g_wT + cbn);
            const float4* qsrc = (const float4*)(g_qT + cbn);
            uint32_t wdst = smb + (OFF_W0 + nb*16384)*4;
            uint32_t qdst = smb + (OFF_Q0 + nb*16384)*4;
            #pragma unroll
            for (int it = 0; it < 4; it++) {
                int idx = tid + it*512;
                cpa16(wdst + idx*16, wsrc + idx);
                cpa16(qdst + idx*16, qsrc + idx);
            }
            if (tid < 256) {
                const float* usrc = g_u + cbn + (tid>>3)*DV + v0 + (tid&7)*4;
                uint32_t udst = smb + (OFF_U0 + nb*1152 + (tid>>3)*36 + (tid&7)*4)*4;
                cpa16(udst, usrc);
                const float* asrc = g_attnT + ((long)bh*NCH + tn)*CC*CC + tid*4;
                uint32_t adst = smb + (OFF_A0 + nb*1152 + (tid>>3)*36 + (tid&7)*4)*4;
                cpa16(adst, asrc);
            }
            CP_COMMIT();
        }

        const float* wb = sm + OFF_W0 + bsel*16384;
        const float* qb = sm + OFF_Q0 + bsel*16384;
        const float* ub = sm + OFF_U0 + bsel*1152;
        const float* ab = sm + OFF_A0 + bsel*1152;

        // ---- phase 1: u = w.S, o = q.S ; k-split across two warp groups ----
        // warp group ks = wid>>3 handles k in [ks*128, ks*128+128)
        // rows c = 4*(wid&7)..+3, col v = lane
        const int ks = wid >> 3;
        const int cr = (wid & 7) * 4;
        ull U01 = 0, U23 = 0, O01 = 0, O23 = 0;
        {
            const int k0 = ks * 128;
            #pragma unroll 8
            for (int kk = 0; kk < 128; kk++) {
                const int k = k0 + kk;
                float s = Ss[k*36 + lane];
                ull ssp = pk2(s, s);
                ulonglong2 w2 = *(const ulonglong2*)&wb[k*32 + cr];
                ulonglong2 q2 = *(const ulonglong2*)&qb[k*32 + cr];
                ffma2(U01, w2.x, ssp);
                ffma2(U23, w2.y, ssp);
                ffma2(O01, q2.x, ssp);
                ffma2(O23, q2.y, ssp);
            }
        }
        // group B (ks==1) publishes partials
        if (ks == 1) {
            float2 u01 = up2(U01), u23 = up2(U23);
            float2 o01 = up2(O01), o23 = up2(O23);
            us[(cr+0)*36 + lane] = u01.x;
            us[(cr+1)*36 + lane] = u01.y;
            us[(cr+2)*36 + lane] = u23.x;
            us[(cr+3)*36 + lane] = u23.y;
            po[(cr+0)*36 + lane] = o01.x;
            po[(cr+1)*36 + lane] = o01.y;
            po[(cr+2)*36 + lane] = o23.x;
            po[(cr+3)*36 + lane] = o23.y;
        }
        __syncthreads();
        // group A (ks==0) combines: us = u_raw - (uA + uB); po = oA + oB
        if (ks == 0) {
            float2 u01 = up2(U01), u23 = up2(U23);
            float2 o01 = up2(O01), o23 = up2(O23);
            us[(cr+0)*36 + lane] = ub[(cr+0)*36 + lane] - (u01.x + us[(cr+0)*36 + lane]);
            us[(cr+1)*36 + lane] = ub[(cr+1)*36 + lane] - (u01.y + us[(cr+1)*36 + lane]);
            us[(cr+2)*36 + lane] = ub[(cr+2)*36 + lane] - (u23.x + us[(cr+2)*36 + lane]);
            us[(cr+3)*36 + lane] = ub[(cr+3)*36 + lane] - (u23.y + us[(cr+3)*36 + lane]);
            po[(cr+0)*36 + lane] += o01.x;
            po[(cr+1)*36 + lane] += o01.y;
            po[(cr+2)*36 + lane] += o23.x;
            po[(cr+3)*36 + lane] += o23.y;
        }
        __syncthreads();

        // ---- phase 2: o = po + attn_local . u ; warp = 2 c-rows ----
        {
            const int c2 = wid * 2;
            float o0 = po[(c2+0)*36 + lane];
            float o1 = po[(c2+1)*36 + lane];
            #pragma unroll 8
            for (int d = 0; d < 32; d++) {
                float uu = us[d*36 + lane];
                float2 a2 = *(const float2*)&ab[d*36 + c2];
                o0 += a2.x * uu;
                o1 += a2.y * uu;
            }
            float* op = outp + ((long)bh*LSEQ + (long)t*CC)*DV;
            op[(c2+0)*DV + v0 + lane] = o0;
            op[(c2+1)*DV + v0 + lane] = o1;
        }

        // wait for kn(t) (G(t+1) may still be pending)
        if (t + 1 < NCH) { CP_WAIT1(); } else { CP_WAIT0(); }
        __syncthreads();

        // ---- phase 3: S = gm*S + kn^T.u ----
        // thread: k = (wid&7)*32 + lane ; v = vg..vg+15 where vg = (wid>>3)*16
        {
            const int kx = (wid & 7)*32 + lane;
            const int vg = (wid >> 3)*16;
            ull accP[8];
            #pragma unroll
            for (int z = 0; z < 8; z++) accP[z] = 0ull;
            #pragma unroll 4
            for (int c = 0; c < 32; c++) {
                float kv = kb[c*DK + kx];
                ull kvp = pk2(kv, kv);
                ulonglong2 ua = *(const ulonglong2*)&us[c*36 + vg];
                ulonglong2 ubp = *(const ulonglong2*)&us[c*36 + vg + 4];
                ulonglong2 uc = *(const ulonglong2*)&us[c*36 + vg + 8];
                ulonglong2 ud = *(const ulonglong2*)&us[c*36 + vg + 12];
                ffma2(accP[0], kvp, ua.x);
                ffma2(accP[1], kvp, ua.y);
                ffma2(accP[2], kvp, ubp.x);
                ffma2(accP[3], kvp, ubp.y);
                ffma2(accP[4], kvp, uc.x);
                ffma2(accP[5], kvp, uc.y);
                ffma2(accP[6], kvp, ud.x);
                ffma2(accP[7], kvp, ud.y);
            }
            const float gm = g_gm[bh*NCH + t];
            const ull gmp = pk2(gm, gm);
            const bool last = (t == NCH-1);
            float* sfp = sFinal + (long)bh*DK*DV;
            #pragma unroll
            for (int j = 0; j < 4; j++) {
                ulonglong2 so = *(const ulonglong2*)&Ss[kx*36 + vg + j*4];
                ull n0 = accP[j*2+0], n1 = accP[j*2+1];
                ffma2(n0, so.x, gmp);
                ffma2(n1, so.y, gmp);
                ulonglong2 sn; sn.x = n0; sn.y = n1;
                *(ulonglong2*)&Ss[kx*36 + vg + j*4] = sn;
                if (last) *(ulonglong2*)&sfp[(long)kx*DV + v0 + vg + j*4] = sn;
            }
        }
        // loop top's __syncthreads orders phase-3 S writes vs next phase 1
    }
}

// ================= launch =================
extern "C" void kernel_launch(void* const* d_in, const int* in_sizes, int n_in,
                              void* d_out, int out_size) {
    const float* q     = (const float*)d_in[0];
    const float* k     = (const float*)d_in[1];
    const float* v     = (const float*)d_in[2];
    const float* beta  = (const float*)d_in[3];
    const float* gamma = (const float*)d_in[4];
    float* outp = (float*)d_out;
    float* sfin = outp + (long)BHn*LSEQ*DV;   // S appended after out

    cudaFuncSetAttribute(pre_kernel,  cudaFuncAttributeMaxDynamicSharedMemorySize,
                         PRE_SMEM_FLOATS*4);
    cudaFuncSetAttribute(scan_kernel, cudaFuncAttributeMaxDynamicSharedMemorySize,
                         SCAN_SMEM_FLOATS*4);
    (void)in_sizes; (void)n_in; (void)out_size;

    pre_kernel<<<BHn*NCH, 256, PRE_SMEM_FLOATS*4>>>(q, k, v, beta, gamma);
    scan_kernel<<<dim3(8, BHn), 512, SCAN_SMEM_FLOATS*4>>>(outp, sfin);
}

// round 4
// speedup vs baseline: 1.9125x; 1.2142x over previous
#include <cuda_runtime.h>
#include <cuda_bf16.h>
#include <cstdint>

// DeltaNet chunkwise delta-rule linear attention with decay.
// b=4 h=4 (BH=16), L=4096, dk=dv=256, chunk C=32, NCH=128 chunks.
//
//  pre_kernel  : per-chunk parallel precompute (norms, T via forward subst, u_raw, w, attn, gamma-mean)
//  scan_kernel : ONE persistent launch. 128 CTAs (16 bh x 8 v-blocks), 512 thr.
//                Register-tiled GEMM phases (f32x2), wavefront-economical LDS,
//                cp.async prefetch (W/Q single-buffered, K/U/A double-buffered).

#define BHn 16
#define LSEQ 4096
#define DK 256
#define DV 256
#define CC 32
#define NCH 128
#define CHELEM (CC*DK)          // 8192 floats per chunk per tensor

// -------- scratch (device globals; no allocation allowed) --------
__device__ float g_qT[BHn*NCH*CHELEM];     // [bh][ch][k][c]  (k-major)
__device__ float g_kn[BHn*NCH*CHELEM];     // [bh][ch][c][k]  (c-major)
__device__ float g_wT[BHn*NCH*CHELEM];     // [bh][ch][k][c]
__device__ float g_u [BHn*NCH*CHELEM];     // [bh][ch][c][v]  (u_raw)
__device__ float g_attnT[BHn*NCH*CC*CC];   // [bh][ch][d][c] = attn[c][d] (masked d<=c)
__device__ float g_gm[BHn*NCH];

// ---------- packed f32x2 helpers ----------
typedef unsigned long long ull;

__device__ __forceinline__ void ffma2(ull &d, ull a, ull b) {
    asm("fma.rn.f32x2 %0, %1, %2, %0;" : "+l"(d) : "l"(a), "l"(b));
}
__device__ __forceinline__ void fadd2(ull &d, ull a) {
    asm("add.rn.f32x2 %0, %0, %1;" : "+l"(d) : "l"(a));
}
__device__ __forceinline__ ull pk2(float a, float b) {
    ull r; asm("mov.b64 %0, {%1, %2};" : "=l"(r) : "f"(a), "f"(b)); return r;
}
__device__ __forceinline__ float2 up2(ull p) {
    float2 r; asm("mov.b64 {%0, %1}, %2;" : "=f"(r.x), "=f"(r.y) : "l"(p)); return r;
}
__device__ __forceinline__ uint32_t smem_u32(const void* p) {
    uint32_t a;
    asm("{ .reg .u64 t; cvta.to.shared.u64 t, %1; cvt.u32.u64 %0, t; }" : "=r"(a) : "l"(p));
    return a;
}
__device__ __forceinline__ void cpa16(uint32_t dst, const void* src) {
    asm volatile("cp.async.cg.shared.global [%0], [%1], 16;" :: "r"(dst), "l"(src));
}
#define CP_COMMIT() asm volatile("cp.async.commit_group;")
#define CP_WAIT0()  asm volatile("cp.async.wait_group 0;")

// ================= preprocess =================
#define PRE_SMEM_FLOATS (8320+8320+1056+32+32)

__global__ void pre_kernel(const float* __restrict__ q, const float* __restrict__ k,
                           const float* __restrict__ v, const float* __restrict__ beta,
                           const float* __restrict__ gamma) {
    extern __shared__ float sm[];
    float* qs = sm;              // 32*260
    float* ks = sm + 8320;       // 32*260
    float* As = sm + 16640;      // 32*33
    float* bs = sm + 17696;      // 32
    float* gs = sm + 17728;      // 32

    const int tid  = threadIdx.x;
    const int lane = tid & 31;
    const int wid  = tid >> 5;
    const int bh = blockIdx.x >> 7;
    const int ch = blockIdx.x & 127;
    const long tok0 = (long)bh*LSEQ + (long)ch*CC;

    const float* qg = q + tok0*DK;
    const float* kg = k + tok0*DK;

    #pragma unroll 8
    for (int i = 0; i < 32; i++) {
        qs[i*260 + tid] = qg[i*DK + tid];
        ks[i*260 + tid] = kg[i*DK + tid];
    }
    if (tid < 32) { bs[tid] = beta[tok0 + tid]; gs[tid] = gamma[tok0 + tid]; }
    __syncthreads();

    // l2 normalize rows (warp per row)
    for (int r = wid; r < 32; r += 8) {
        float s = 0.f;
        #pragma unroll
        for (int x = lane; x < 256; x += 32) { float t = qs[r*260+x]; s += t*t; }
        s += __shfl_xor_sync(0xffffffffu, s, 16);
        s += __shfl_xor_sync(0xffffffffu, s, 8);
        s += __shfl_xor_sync(0xffffffffu, s, 4);
        s += __shfl_xor_sync(0xffffffffu, s, 2);
        s += __shfl_xor_sync(0xffffffffu, s, 1);
        float inv = rsqrtf(s + 1e-6f);
        #pragma unroll
        for (int x = lane; x < 256; x += 32) qs[r*260+x] *= inv;

        float s2 = 0.f;
        #pragma unroll
        for (int x = lane; x < 256; x += 32) { float t = ks[r*260+x]; s2 += t*t; }
        s2 += __shfl_xor_sync(0xffffffffu, s2, 16);
        s2 += __shfl_xor_sync(0xffffffffu, s2, 8);
        s2 += __shfl_xor_sync(0xffffffffu, s2, 4);
        s2 += __shfl_xor_sync(0xffffffffu, s2, 2);
        s2 += __shfl_xor_sync(0xffffffffu, s2, 1);
        float inv2 = rsqrtf(s2 + 1e-6f);
        #pragma unroll
        for (int x = lane; x < 256; x += 32) ks[r*260+x] *= inv2;
    }
    __syncthreads();

    const long cb = ((long)bh*NCH + ch)*CHELEM;

    // write kn (c-major) and qT (k-major)
    {
        float* knp = g_kn + cb;
        #pragma unroll 8
        for (int i = 0; i < 32; i++) knp[i*DK + tid] = ks[i*260 + tid];
        #pragma unroll
        for (int g2 = 0; g2 < 8; g2++) {
            float4 t4 = make_float4(qs[(g2*4+0)*260+tid], qs[(g2*4+1)*260+tid],
                                    qs[(g2*4+2)*260+tid], qs[(g2*4+3)*260+tid]);
            *(float4*)&g_qT[cb + (long)tid*32 + g2*4] = t4;
        }
    }

    // A = -beta_i*(kn_i.kn_j) (j<i) ; attnT[j][i] = (j<=i)? qn_i.kn_j : 0
    {
        float* atp = g_attnT + ((long)bh*NCH + ch)*CC*CC;
        #pragma unroll
        for (int p = 0; p < 4; p++) {
            int j = p*8 + wid;
            int i = lane;
            float accA = 0.f, accQ = 0.f;
            #pragma unroll 8
            for (int k4 = 0; k4 < 64; k4++) {
                float4 kj = *(float4*)&ks[j*260 + k4*4];
                float4 ki = *(float4*)&ks[i*260 + k4*4];
                float4 qi = *(float4*)&qs[i*260 + k4*4];
                accA += ki.x*kj.x + ki.y*kj.y + ki.z*kj.z + ki.w*kj.w;
                accQ += qi.x*kj.x + qi.y*kj.y + qi.z*kj.z + qi.w*kj.w;
            }
            if (j < i) As[i*33 + j] = -bs[i]*accA;
            atp[j*32 + i] = (j <= i) ? accQ : 0.0f;
        }
    }
    __syncthreads();

    // forward substitution (warp 0): strict-lower T in As
    if (wid == 0) {
        int col = lane;
        for (int i = 1; i < 32; i++) {
            float inc = 0.f;
            if (col < i) {
                for (int j = col+1; j < i; j++) inc += As[i*33+j]*As[j*33+col];
            }
            __syncwarp();
            if (col < i) As[i*33+col] += inc;
            __syncwarp();
        }
    }
    if (wid == 1) {
        float g2 = gs[lane];
        g2 += __shfl_xor_sync(0xffffffffu, g2, 16);
        g2 += __shfl_xor_sync(0xffffffffu, g2, 8);
        g2 += __shfl_xor_sync(0xffffffffu, g2, 4);
        g2 += __shfl_xor_sync(0xffffffffu, g2, 2);
        g2 += __shfl_xor_sync(0xffffffffu, g2, 1);
        if (lane == 0) g_gm[bh*NCH + ch] = g2 * (1.0f/32.0f);
    }
    __syncthreads();

    // u_raw = T (beta*v)
    {
        float colv[32];
        const float* vg = v + tok0*DV;
        #pragma unroll
        for (int j = 0; j < 32; j++) colv[j] = vg[j*DV + tid] * bs[j];
        float* up = g_u + cb;
        #pragma unroll
        for (int i = 0; i < 32; i++) {
            float acc = colv[i];
            #pragma unroll
            for (int j = 0; j < i; j++) acc += As[i*33+j]*colv[j];
            up[i*DV + tid] = acc;
        }
    }
    // w = T (beta*kn), k-major
    {
        float colk[32];
        #pragma unroll
        for (int j = 0; j < 32; j++) colk[j] = ks[j*260 + tid] * bs[j];
        float wout[32];
        #pragma unroll
        for (int i = 0; i < 32; i++) {
            float acc = colk[i];
            #pragma unroll
            for (int j = 0; j < i; j++) acc += As[i*33+j]*colk[j];
            wout[i] = acc;
        }
        #pragma unroll
        for (int g2 = 0; g2 < 8; g2++)
            *(float4*)&g_wT[cb + (long)tid*32 + g2*4] =
                make_float4(wout[g2*4], wout[g2*4+1], wout[g2*4+2], wout[g2*4+3]);
    }
}

// ================= persistent scan (512 threads, register-tiled) =================
// smem float layout:
#define OFF_S   0        // [256][36]  9216
#define OFF_W   9216     // [256][32]  8192 (single buffer)
#define OFF_Q   17408    // [256][32]  8192 (single buffer)
#define OFF_K   25600    // [2][32][256] 16384
#define OFF_U   41984    // [2][32][36]  2304
#define OFF_A   44288    // [2][32][36]  2304
#define OFF_RED 46592    // [2][2048]    4096 (slice partial blocks)
#define OFF_US  50688    // [32][36]     1152
#define OFF_PO  51840    // [32][36]     1152
#define SCAN_SMEM_FLOATS 52992   // 211968 bytes

__global__ __launch_bounds__(512, 1)
void scan_kernel(float* __restrict__ outp, float* __restrict__ sFinal) {
    extern __shared__ float sm[];
    const uint32_t smb = smem_u32(sm);

    const int tid  = threadIdx.x;
    const int bh = blockIdx.y;
    const int v0 = blockIdx.x * 32;

    float* Ss = sm + OFF_S;
    float* us = sm + OFF_US;
    float* po = sm + OFF_PO;

    const long bhoff = (long)bh*NCH*CHELEM;

    // phase-1 mapping: 4 k-slices x 128 threads; thread tile 2c x 4v
    const int slice = tid >> 7;        // 0..3
    const int t128  = tid & 127;
    const int cp2   = t128 >> 3;       // 0..15 -> c = cp2*2
    const int vp    = t128 & 7;        // v = vp*4
    const int c0    = cp2*2;
    const int vv    = vp*4;

    // phase-2 mapping: 1c x 2v
    const int c_p2 = tid >> 4;         // 0..31
    const int v_p2 = (tid & 15)*2;

    // phase-3 mapping: 4k x 4v
    const int kx3 = (tid >> 3)*4;      // 0..252 step 4
    const int vv3 = (tid & 7)*4;

    // zero resident S slice
    #pragma unroll
    for (int i = 0; i < 18; i++) Ss[tid + i*512] = 0.0f;

    // ---- preload chunk 0: W, Q, K(buf0), U(buf0), A(buf0) ----
    {
        const long cb = bhoff;
        const float4* wsrc = (const float4*)(g_wT + cb);
        const float4* qsrc = (const float4*)(g_qT + cb);
        const float4* ksrc = (const float4*)(g_kn + cb);
        #pragma unroll
        for (int it = 0; it < 4; it++) {
            int idx = tid + it*512;
            cpa16(smb + OFF_W*4 + idx*16, wsrc + idx);
            cpa16(smb + OFF_Q*4 + idx*16, qsrc + idx);
            cpa16(smb + OFF_K*4 + idx*16, ksrc + idx);
        }
        if (tid < 256) {
            const float* usrc = g_u + cb + (tid>>3)*DV + v0 + (tid&7)*4;
            cpa16(smb + (OFF_U + (tid>>3)*36 + (tid&7)*4)*4, usrc);
            const float* asrc = g_attnT + (long)bh*NCH*CC*CC + tid*4;
            cpa16(smb + (OFF_A + (tid>>3)*36 + (tid&7)*4)*4, asrc);
        }
        CP_COMMIT();
    }

    for (int t = 0; t < NCH; t++) {
        CP_WAIT0();
        __syncthreads();   // all chunk-t operands visible; S(t-1) update visible

        const int bsel = t & 1;

        // ---- issue K/U/A(t+1) prefetch (different buffers than t) ----
        if (t + 1 < NCH) {
            const int tn = t + 1, nb = tn & 1;
            const long cbn = bhoff + (long)tn*CHELEM;
            const float4* ksrc = (const float4*)(g_kn + cbn);
            uint32_t kdst = smb + (OFF_K + nb*8192)*4;
            #pragma unroll
            for (int it = 0; it < 4; it++) {
                int idx = tid + it*512;
                cpa16(kdst + idx*16, ksrc + idx);
            }
            if (tid < 256) {
                const float* usrc = g_u + cbn + (tid>>3)*DV + v0 + (tid&7)*4;
                cpa16(smb + (OFF_U + nb*1152 + (tid>>3)*36 + (tid&7)*4)*4, usrc);
                const float* asrc = g_attnT + ((long)bh*NCH + tn)*CC*CC + tid*4;
                cpa16(smb + (OFF_A + nb*1152 + (tid>>3)*36 + (tid&7)*4)*4, asrc);
            }
            CP_COMMIT();
        }

        const float* wb = sm + OFF_W;
        const float* qb = sm + OFF_Q;

        // ==== phase 1: u = W.S, o = Q.S  (k-sliced register tiles) ====
        ull ua0=0,ua1=0,ua2=0,ua3=0, oa0=0,oa1=0,oa2=0,oa3=0;
        {
            const int kbase = slice*64;
            #pragma unroll 4
            for (int kk = 0; kk < 64; kk++) {
                const int k = kbase + kk;
                float4 s4 = *(const float4*)&Ss[k*36 + vv];
                ull s01 = pk2(s4.x, s4.y), s23 = pk2(s4.z, s4.w);
                float2 w2 = *(const float2*)&wb[k*32 + c0];
                float2 q2 = *(const float2*)&qb[k*32 + c0];
                ull wx = pk2(w2.x, w2.x);
                ffma2(ua0, wx, s01); ffma2(ua1, wx, s23);
                ull wy = pk2(w2.y, w2.y);
                ffma2(ua2, wy, s01); ffma2(ua3, wy, s23);
                ull qx = pk2(q2.x, q2.x);
                ffma2(oa0, qx, s01); ffma2(oa1, qx, s23);
                ull qy = pk2(q2.y, q2.y);
                ffma2(oa2, qy, s01); ffma2(oa3, qy, s23);
            }
        }
        // slices 2,3 publish partials to RED blocks 0,1
        if (slice >= 2) {
            float* red = sm + OFF_RED + (slice-2)*2048;
            float2 a0 = up2(ua0), a1 = up2(ua1), a2 = up2(ua2), a3 = up2(ua3);
            float2 b0 = up2(oa0), b1 = up2(oa1), b2 = up2(oa2), b3 = up2(oa3);
            *(float4*)&red[c0*32 + vv]           = make_float4(a0.x,a0.y,a1.x,a1.y);
            *(float4*)&red[(c0+1)*32 + vv]       = make_float4(a2.x,a2.y,a3.x,a3.y);
            *(float4*)&red[1024 + c0*32 + vv]    = make_float4(b0.x,b0.y,b1.x,b1.y);
            *(float4*)&red[1024 + (c0+1)*32 + vv]= make_float4(b2.x,b2.y,b3.x,b3.y);
        }
        __syncthreads();

        // ---- issue W/Q(t+1) prefetch now that phase-1 reads are done ----
        if (t + 1 < NCH) {
            const long cbn = bhoff + (long)(t+1)*CHELEM;
            const float4* wsrc = (const float4*)(g_wT + cbn);
            const float4* qsrc = (const float4*)(g_qT + cbn);
            #pragma unroll
            for (int it = 0; it < 4; it++) {
                int idx = tid + it*512;
                cpa16(smb + OFF_W*4 + idx*16, wsrc + idx);
                cpa16(smb + OFF_Q*4 + idx*16, qsrc + idx);
            }
            CP_COMMIT();
        }

        // round A: slice 0 += RED[0] (slice2); slice 1 += RED[1] (slice3), then store to RED[1]
        if (slice < 2) {
            const float* red = sm + OFF_RED + slice*2048;
            float4 ru0 = *(const float4*)&red[c0*32 + vv];
            float4 ru1 = *(const float4*)&red[(c0+1)*32 + vv];
            float4 ro0 = *(const float4*)&red[1024 + c0*32 + vv];
            float4 ro1 = *(const float4*)&red[1024 + (c0+1)*32 + vv];
            fadd2(ua0, pk2(ru0.x,ru0.y)); fadd2(ua1, pk2(ru0.z,ru0.w));
            fadd2(ua2, pk2(ru1.x,ru1.y)); fadd2(ua3, pk2(ru1.z,ru1.w));
            fadd2(oa0, pk2(ro0.x,ro0.y)); fadd2(oa1, pk2(ro0.z,ro0.w));
            fadd2(oa2, pk2(ro1.x,ro1.y)); fadd2(oa3, pk2(ro1.z,ro1.w));
        }
        if (slice == 1) {
            float* red = sm + OFF_RED + 2048;
            float2 a0 = up2(ua0), a1 = up2(ua1), a2 = up2(ua2), a3 = up2(ua3);
            float2 b0 = up2(oa0), b1 = up2(oa1), b2 = up2(oa2), b3 = up2(oa3);
            *(float4*)&red[c0*32 + vv]           = make_float4(a0.x,a0.y,a1.x,a1.y);
            *(float4*)&red[(c0+1)*32 + vv]       = make_float4(a2.x,a2.y,a3.x,a3.y);
            *(float4*)&red[1024 + c0*32 + vv]    = make_float4(b0.x,b0.y,b1.x,b1.y);
            *(float4*)&red[1024 + (c0+1)*32 + vv]= make_float4(b2.x,b2.y,b3.x,b3.y);
        }
        __syncthreads();

        // round B: slice 0 adds RED[1] -> final; computes us = u_raw - u, po = o
        if (slice == 0) {
            const float* red = sm + OFF_RED + 2048;
            float4 ru0 = *(const float4*)&red[c0*32 + vv];
            float4 ru1 = *(const float4*)&red[(c0+1)*32 + vv];
            float4 ro0 = *(const float4*)&red[1024 + c0*32 + vv];
            float4 ro1 = *(const float4*)&red[1024 + (c0+1)*32 + vv];
            fadd2(ua0, pk2(ru0.x,ru0.y)); fadd2(ua1, pk2(ru0.z,ru0.w));
            fadd2(ua2, pk2(ru1.x,ru1.y)); fadd2(ua3, pk2(ru1.z,ru1.w));
            fadd2(oa0, pk2(ro0.x,ro0.y)); fadd2(oa1, pk2(ro0.z,ro0.w));
            fadd2(oa2, pk2(ro1.x,ro1.y)); fadd2(oa3, pk2(ro1.z,ro1.w));

            const float* ub = sm + OFF_U + bsel*1152;
            float4 ur0 = *(const float4*)&ub[c0*36 + vv];
            float4 ur1 = *(const float4*)&ub[(c0+1)*36 + vv];
            float2 u0 = up2(ua0), u1 = up2(ua1), u2 = up2(ua2), u3 = up2(ua3);
            *(float4*)&us[c0*36 + vv] =
                make_float4(ur0.x-u0.x, ur0.y-u0.y, ur0.z-u1.x, ur0.w-u1.y);
            *(float4*)&us[(c0+1)*36 + vv] =
                make_float4(ur1.x-u2.x, ur1.y-u2.y, ur1.z-u3.x, ur1.w-u3.y);
            float2 o0 = up2(oa0), o1 = up2(oa1), o2 = up2(oa2), o3 = up2(oa3);
            *(float4*)&po[c0*36 + vv]     = make_float4(o0.x,o0.y,o1.x,o1.y);
            *(float4*)&po[(c0+1)*36 + vv] = make_float4(o2.x,o2.y,o3.x,o3.y);
        }
        __syncthreads();

        // ==== phase 2: o = po + attn_local . u ====
        {
            const float* ab = sm + OFF_A + bsel*1152;
            float2 pv = *(const float2*)&po[c_p2*36 + v_p2];
            ull oacc = pk2(pv.x, pv.y);
            #pragma unroll 8
            for (int d = 0; d < 32; d++) {
                float2 u2 = *(const float2*)&us[d*36 + v_p2];
                float av = ab[d*36 + c_p2];
                ffma2(oacc, pk2(av, av), pk2(u2.x, u2.y));
            }
            float2 r = up2(oacc);
            *(float2*)(outp + ((long)bh*LSEQ + (long)t*CC + c_p2)*DV + v0 + v_p2) = r;
        }

        // ==== phase 3: S = gm*S + kn^T . u ====
        {
            const float* kb = sm + OFF_K + bsel*8192;
            ull acc0=0,acc1=0,acc2=0,acc3=0,acc4=0,acc5=0,acc6=0,acc7=0;
            #pragma unroll 4
            for (int c = 0; c < 32; c++) {
                float4 kv4 = *(const float4*)&kb[c*256 + kx3];
                float4 u4  = *(const float4*)&us[c*36 + vv3];
                ull u01 = pk2(u4.x, u4.y), u23 = pk2(u4.z, u4.w);
                ull p0 = pk2(kv4.x, kv4.x); ffma2(acc0, p0, u01); ffma2(acc1, p0, u23);
                ull p1 = pk2(kv4.y, kv4.y); ffma2(acc2, p1, u01); ffma2(acc3, p1, u23);
                ull p2 = pk2(kv4.z, kv4.z); ffma2(acc4, p2, u01); ffma2(acc5, p2, u23);
                ull p3 = pk2(kv4.w, kv4.w); ffma2(acc6, p3, u01); ffma2(acc7, p3, u23);
            }
            const float gm = g_gm[bh*NCH + t];
            const ull gmp = pk2(gm, gm);
            const bool last = (t == NCH-1);
            float* sfp = sFinal + (long)bh*DK*DV;
            #pragma unroll
            for (int r = 0; r < 4; r++) {
                const int row = kx3 + r;
                ulonglong2 so = *(const ulonglong2*)&Ss[row*36 + vv3];
                ull n0, n1;
                switch (r) {
                    case 0: n0 = acc0; n1 = acc1; break;
                    case 1: n0 = acc2; n1 = acc3; break;
                    case 2: n0 = acc4; n1 = acc5; break;
                    default: n0 = acc6; n1 = acc7; break;
                }
                ffma2(n0, so.x, gmp);
                ffma2(n1, so.y, gmp);
                ulonglong2 sn; sn.x = n0; sn.y = n1;
                *(ulonglong2*)&Ss[row*36 + vv3] = sn;
                if (last) *(ulonglong2*)&sfp[(long)row*DV + v0 + vv3] = sn;
            }
        }
        // loop-top __syncthreads orders phase-3 S writes vs next phase 1
    }
}

// ================= launch =================
extern "C" void kernel_launch(void* const* d_in, const int* in_sizes, int n_in,
                              void* d_out, int out_size) {
    const float* q     = (const float*)d_in[0];
    const float* k     = (const float*)d_in[1];
    const float* v     = (const float*)d_in[2];
    const float* beta  = (const float*)d_in[3];
    const float* gamma = (const float*)d_in[4];
    float* outp = (float*)d_out;
    float* sfin = outp + (long)BHn*LSEQ*DV;   // S appended after out

    cudaFuncSetAttribute(pre_kernel,  cudaFuncAttributeMaxDynamicSharedMemorySize,
                         PRE_SMEM_FLOATS*4);
    cudaFuncSetAttribute(scan_kernel, cudaFuncAttributeMaxDynamicSharedMemorySize,
                         SCAN_SMEM_FLOATS*4);
    (void)in_sizes; (void)n_in; (void)out_size;

    pre_kernel<<<BHn*NCH, 256, PRE_SMEM_FLOATS*4>>>(q, k, v, beta, gamma);
    scan_kernel<<<dim3(8, BHn), 512, SCAN_SMEM_FLOATS*4>>>(outp, sfin);
}

// round 5
// speedup vs baseline: 2.1574x; 1.1280x over previous
#include <cuda_runtime.h>
#include <cuda_bf16.h>
#include <cstdint>

// DeltaNet chunkwise delta-rule linear attention with decay.
// b=4 h=4 (BH=16), L=4096, dk=dv=256, chunk C=32, NCH=128 chunks.
//
//  pre_kernel  : per-chunk parallel precompute. Gram section uses warp-per-4-rows
//                mapping (broadcast-friendly LDS). W and Q stored INTERLEAVED (g_wq).
//  scan_kernel : ONE persistent launch. 128 CTAs (16 bh x 8 v-blocks), 512 thr.
//                Register-tiled GEMM phases (f32x2); phase-1 reads one fused WQ float4.

#define BHn 16
#define LSEQ 4096
#define DK 256
#define DV 256
#define CC 32
#define NCH 128
#define CHELEM (CC*DK)          // 8192 floats per chunk per tensor

// -------- scratch (device globals; no allocation allowed) --------
__device__ float g_wq[BHn*NCH*2*CHELEM];   // [bh][ch][k][64]: {w[k,2c],w[k,2c+1],q[k,2c],q[k,2c+1]}
__device__ float g_kn[BHn*NCH*CHELEM];     // [bh][ch][c][k]  (c-major)
__device__ float g_u [BHn*NCH*CHELEM];     // [bh][ch][c][v]  (u_raw)
__device__ float g_attn[BHn*NCH*CC*CC];    // [bh][ch][c][d] = attn (masked d<=c)
__device__ float g_gm[BHn*NCH];

// ---------- packed f32x2 helpers ----------
typedef unsigned long long ull;

__device__ __forceinline__ void ffma2(ull &d, ull a, ull b) {
    asm("fma.rn.f32x2 %0, %1, %2, %0;" : "+l"(d) : "l"(a), "l"(b));
}
__device__ __forceinline__ void fadd2(ull &d, ull a) {
    asm("add.rn.f32x2 %0, %0, %1;" : "+l"(d) : "l"(a));
}
__device__ __forceinline__ ull pk2(float a, float b) {
    ull r; asm("mov.b64 %0, {%1, %2};" : "=l"(r) : "f"(a), "f"(b)); return r;
}
__device__ __forceinline__ float2 up2(ull p) {
    float2 r; asm("mov.b64 {%0, %1}, %2;" : "=f"(r.x), "=f"(r.y) : "l"(p)); return r;
}
__device__ __forceinline__ uint32_t smem_u32(const void* p) {
    uint32_t a;
    asm("{ .reg .u64 t; cvta.to.shared.u64 t, %1; cvt.u32.u64 %0, t; }" : "=r"(a) : "l"(p));
    return a;
}
__device__ __forceinline__ void cpa16(uint32_t dst, const void* src) {
    asm volatile("cp.async.cg.shared.global [%0], [%1], 16;" :: "r"(dst), "l"(src));
}
#define CP_COMMIT() asm volatile("cp.async.commit_group;")
#define CP_WAIT0()  asm volatile("cp.async.wait_group 0;")

// ================= preprocess =================
#define PRE_SMEM_FLOATS (8320+8320+1056+32+32)

__global__ void pre_kernel(const float* __restrict__ q, const float* __restrict__ k,
                           const float* __restrict__ v, const float* __restrict__ beta,
                           const float* __restrict__ gamma) {
    extern __shared__ float sm[];
    float* qs = sm;              // 32*260
    float* ks = sm + 8320;       // 32*260
    float* As = sm + 16640;      // 32*33
    float* bs = sm + 17696;      // 32
    float* gs = sm + 17728;      // 32

    const int tid  = threadIdx.x;
    const int lane = tid & 31;
    const int wid  = tid >> 5;
    const int bh = blockIdx.x >> 7;
    const int ch = blockIdx.x & 127;
    const long tok0 = (long)bh*LSEQ + (long)ch*CC;

    const float* qg = q + tok0*DK;
    const float* kg = k + tok0*DK;

    #pragma unroll 8
    for (int i = 0; i < 32; i++) {
        qs[i*260 + tid] = qg[i*DK + tid];
        ks[i*260 + tid] = kg[i*DK + tid];
    }
    if (tid < 32) { bs[tid] = beta[tok0 + tid]; gs[tid] = gamma[tok0 + tid]; }
    __syncthreads();

    // l2 normalize rows (warp per row)
    for (int r = wid; r < 32; r += 8) {
        float s = 0.f;
        #pragma unroll
        for (int x = lane; x < 256; x += 32) { float t = qs[r*260+x]; s += t*t; }
        s += __shfl_xor_sync(0xffffffffu, s, 16);
        s += __shfl_xor_sync(0xffffffffu, s, 8);
        s += __shfl_xor_sync(0xffffffffu, s, 4);
        s += __shfl_xor_sync(0xffffffffu, s, 2);
        s += __shfl_xor_sync(0xffffffffu, s, 1);
        float inv = rsqrtf(s + 1e-6f);
        #pragma unroll
        for (int x = lane; x < 256; x += 32) qs[r*260+x] *= inv;

        float s2 = 0.f;
        #pragma unroll
        for (int x = lane; x < 256; x += 32) { float t = ks[r*260+x]; s2 += t*t; }
        s2 += __shfl_xor_sync(0xffffffffu, s2, 16);
        s2 += __shfl_xor_sync(0xffffffffu, s2, 8);
        s2 += __shfl_xor_sync(0xffffffffu, s2, 4);
        s2 += __shfl_xor_sync(0xffffffffu, s2, 2);
        s2 += __shfl_xor_sync(0xffffffffu, s2, 1);
        float inv2 = rsqrtf(s2 + 1e-6f);
        #pragma unroll
        for (int x = lane; x < 256; x += 32) ks[r*260+x] *= inv2;
    }
    __syncthreads();

    const long cb = ((long)bh*NCH + ch)*CHELEM;

    // write kn (c-major, coalesced)
    {
        float* knp = g_kn + cb;
        #pragma unroll 8
        for (int i = 0; i < 32; i++) knp[i*DK + tid] = ks[i*260 + tid];
    }

    // ---- Gram matrices: warp handles rows i0..i0+3, lanes give all j ----
    // A[i][j] = -beta_i*(kn_i.kn_j) for j<i ; attn[i][j] = (j<=i)? qn_i.kn_j : 0
    {
        float* atp = g_attn + ((long)bh*NCH + ch)*CC*CC;
        const int i0 = wid*4;
        float accA0=0,accA1=0,accA2=0,accA3=0;
        float accQ0=0,accQ1=0,accQ2=0,accQ3=0;
        #pragma unroll 4
        for (int k4 = 0; k4 < 64; k4++) {
            float4 kj = *(float4*)&ks[lane*260 + k4*4];           // scattered (4 wf)
            float4 ki0 = *(float4*)&ks[(i0+0)*260 + k4*4];        // uniform broadcasts
            float4 qi0 = *(float4*)&qs[(i0+0)*260 + k4*4];
            accA0 += ki0.x*kj.x + ki0.y*kj.y + ki0.z*kj.z + ki0.w*kj.w;
            accQ0 += qi0.x*kj.x + qi0.y*kj.y + qi0.z*kj.z + qi0.w*kj.w;
            float4 ki1 = *(float4*)&ks[(i0+1)*260 + k4*4];
            float4 qi1 = *(float4*)&qs[(i0+1)*260 + k4*4];
            accA1 += ki1.x*kj.x + ki1.y*kj.y + ki1.z*kj.z + ki1.w*kj.w;
            accQ1 += qi1.x*kj.x + qi1.y*kj.y + qi1.z*kj.z + qi1.w*kj.w;
            float4 ki2 = *(float4*)&ks[(i0+2)*260 + k4*4];
            float4 qi2 = *(float4*)&qs[(i0+2)*260 + k4*4];
            accA2 += ki2.x*kj.x + ki2.y*kj.y + ki2.z*kj.z + ki2.w*kj.w;
            accQ2 += qi2.x*kj.x + qi2.y*kj.y + qi2.z*kj.z + qi2.w*kj.w;
            float4 ki3 = *(float4*)&ks[(i0+3)*260 + k4*4];
            float4 qi3 = *(float4*)&qs[(i0+3)*260 + k4*4];
            accA3 += ki3.x*kj.x + ki3.y*kj.y + ki3.z*kj.z + ki3.w*kj.w;
            accQ3 += qi3.x*kj.x + qi3.y*kj.y + qi3.z*kj.z + qi3.w*kj.w;
        }
        if (lane < i0+0) As[(i0+0)*33 + lane] = -bs[i0+0]*accA0;
        if (lane < i0+1) As[(i0+1)*33 + lane] = -bs[i0+1]*accA1;
        if (lane < i0+2) As[(i0+2)*33 + lane] = -bs[i0+2]*accA2;
        if (lane < i0+3) As[(i0+3)*33 + lane] = -bs[i0+3]*accA3;
        atp[(i0+0)*32 + lane] = (lane <= i0+0) ? accQ0 : 0.0f;    // coalesced
        atp[(i0+1)*32 + lane] = (lane <= i0+1) ? accQ1 : 0.0f;
        atp[(i0+2)*32 + lane] = (lane <= i0+2) ? accQ2 : 0.0f;
        atp[(i0+3)*32 + lane] = (lane <= i0+3) ? accQ3 : 0.0f;
    }
    __syncthreads();

    // forward substitution (warp 0): strict-lower T in As
    if (wid == 0) {
        int col = lane;
        for (int i = 1; i < 32; i++) {
            float inc = 0.f;
            if (col < i) {
                for (int j = col+1; j < i; j++) inc += As[i*33+j]*As[j*33+col];
            }
            __syncwarp();
            if (col < i) As[i*33+col] += inc;
            __syncwarp();
        }
    }
    if (wid == 1) {
        float g2 = gs[lane];
        g2 += __shfl_xor_sync(0xffffffffu, g2, 16);
        g2 += __shfl_xor_sync(0xffffffffu, g2, 8);
        g2 += __shfl_xor_sync(0xffffffffu, g2, 4);
        g2 += __shfl_xor_sync(0xffffffffu, g2, 2);
        g2 += __shfl_xor_sync(0xffffffffu, g2, 1);
        if (lane == 0) g_gm[bh*NCH + ch] = g2 * (1.0f/32.0f);
    }
    __syncthreads();

    // ---- fused T-apply: u_raw = T(beta*v), w = T(beta*kn), one As read per (i,j) ----
    {
        float colv[32], colk[32];
        const float* vg = v + tok0*DV;
        #pragma unroll
        for (int j = 0; j < 32; j++) {
            float b = bs[j];
            colv[j] = vg[j*DV + tid] * b;
            colk[j] = ks[j*260 + tid] * b;
        }
        float* up = g_u + cb;
        float wout[32];
        #pragma unroll
        for (int i = 0; i < 32; i++) {
            float accV = colv[i];
            float accK = colk[i];
            #pragma unroll
            for (int j = 0; j < i; j++) {
                float a = As[i*33+j];
                accV += a*colv[j];
                accK += a*colk[j];
            }
            up[i*DV + tid] = accV;
            wout[i] = accK;
        }
        // interleaved WQ write: row k=tid, 64 floats {w0,w1,q0,q1}x16
        float* wqp = g_wq + ((long)bh*NCH + ch)*(2*CHELEM) + (long)tid*64;
        #pragma unroll
        for (int cp = 0; cp < 16; cp++) {
            *(float4*)&wqp[cp*4] = make_float4(wout[2*cp], wout[2*cp+1],
                                               qs[(2*cp)*260 + tid], qs[(2*cp+1)*260 + tid]);
        }
    }
}

// ================= persistent scan (512 threads, register-tiled) =================
// smem float layout:
#define OFF_S   0        // [256][36]  9216
#define OFF_WQ  9216     // [256][64]  16384 (single buffer, fused W+Q)
#define OFF_K   25600    // [2][32][256] 16384
#define OFF_U   41984    // [2][32][36]  2304
#define OFF_A   44288    // [2][32][36]  2304
#define OFF_RED 46592    // [2][2048]    4096 (slice partial blocks)
#define OFF_US  50688    // [32][36]     1152
#define OFF_PO  51840    // [32][36]     1152
#define SCAN_SMEM_FLOATS 52992   // 211968 bytes

__global__ __launch_bounds__(512, 1)
void scan_kernel(float* __restrict__ outp, float* __restrict__ sFinal) {
    extern __shared__ float sm[];
    const uint32_t smb = smem_u32(sm);

    const int tid  = threadIdx.x;
    const int bh = blockIdx.y;
    const int v0 = blockIdx.x * 32;

    float* Ss = sm + OFF_S;
    float* us = sm + OFF_US;
    float* po = sm + OFF_PO;

    const long bhoff = (long)bh*NCH*CHELEM;
    const long bhoff2 = (long)bh*NCH*(2*CHELEM);

    // phase-1 mapping: 4 k-slices x 128 threads; thread tile 2c x 4v
    const int slice = tid >> 7;        // 0..3
    const int t128  = tid & 127;
    const int cp2   = t128 >> 3;       // 0..15 -> c = cp2*2
    const int vp    = t128 & 7;        // v = vp*4
    const int c0    = cp2*2;
    const int vv    = vp*4;

    // phase-2 mapping: 1c x 2v
    const int c_p2 = tid >> 4;         // 0..31
    const int v_p2 = (tid & 15)*2;

    // phase-3 mapping: 4k x 4v
    const int kx3 = (tid >> 3)*4;      // 0..252 step 4
    const int vv3 = (tid & 7)*4;

    // zero resident S slice
    #pragma unroll
    for (int i = 0; i < 18; i++) Ss[tid + i*512] = 0.0f;

    // ---- preload chunk 0: WQ, K(buf0), U(buf0), A(buf0) ----
    {
        const float4* wqsrc = (const float4*)(g_wq + bhoff2);
        const float4* ksrc  = (const float4*)(g_kn + bhoff);
        #pragma unroll
        for (int it = 0; it < 8; it++) {
            int idx = tid + it*512;
            cpa16(smb + OFF_WQ*4 + idx*16, wqsrc + idx);
        }
        #pragma unroll
        for (int it = 0; it < 4; it++) {
            int idx = tid + it*512;
            cpa16(smb + OFF_K*4 + idx*16, ksrc + idx);
        }
        if (tid < 256) {
            const float* usrc = g_u + bhoff + (tid>>3)*DV + v0 + (tid&7)*4;
            cpa16(smb + (OFF_U + (tid>>3)*36 + (tid&7)*4)*4, usrc);
            const float* asrc = g_attn + (long)bh*NCH*CC*CC + tid*4;
            cpa16(smb + (OFF_A + (tid>>3)*36 + (tid&7)*4)*4, asrc);
        }
        CP_COMMIT();
    }

    for (int t = 0; t < NCH; t++) {
        CP_WAIT0();
        __syncthreads();   // all chunk-t operands visible; S(t-1) update visible

        const int bsel = t & 1;

        // ---- issue K/U/A(t+1) prefetch (double-buffered) ----
        if (t + 1 < NCH) {
            const int tn = t + 1, nb = tn & 1;
            const long cbn = bhoff + (long)tn*CHELEM;
            const float4* ksrc = (const float4*)(g_kn + cbn);
            uint32_t kdst = smb + (OFF_K + nb*8192)*4;
            #pragma unroll
            for (int it = 0; it < 4; it++) {
                int idx = tid + it*512;
                cpa16(kdst + idx*16, ksrc + idx);
            }
            if (tid < 256) {
                const float* usrc = g_u + cbn + (tid>>3)*DV + v0 + (tid&7)*4;
                cpa16(smb + (OFF_U + nb*1152 + (tid>>3)*36 + (tid&7)*4)*4, usrc);
                const float* asrc = g_attn + ((long)bh*NCH + tn)*CC*CC + tid*4;
                cpa16(smb + (OFF_A + nb*1152 + (tid>>3)*36 + (tid&7)*4)*4, asrc);
            }
            CP_COMMIT();
        }

        const float* wqb = sm + OFF_WQ;

        // ==== phase 1: u = W.S, o = Q.S  (k-sliced register tiles, fused WQ read) ====
        ull ua0=0,ua1=0,ua2=0,ua3=0, oa0=0,oa1=0,oa2=0,oa3=0;
        {
            const int kbase = slice*64;
            #pragma unroll 8
            for (int kk = 0; kk < 64; kk++) {
                const int k = kbase + kk;
                float4 s4 = *(const float4*)&Ss[k*36 + vv];
                ull s01 = pk2(s4.x, s4.y), s23 = pk2(s4.z, s4.w);
                float4 wq = *(const float4*)&wqb[k*64 + cp2*4];
                ull wx = pk2(wq.x, wq.x);
                ffma2(ua0, wx, s01); ffma2(ua1, wx, s23);
                ull wy = pk2(wq.y, wq.y);
                ffma2(ua2, wy, s01); ffma2(ua3, wy, s23);
                ull qx = pk2(wq.z, wq.z);
                ffma2(oa0, qx, s01); ffma2(oa1, qx, s23);
                ull qy = pk2(wq.w, wq.w);
                ffma2(oa2, qy, s01); ffma2(oa3, qy, s23);
            }
        }
        // slices 2,3 publish partials to RED blocks 0,1
        if (slice >= 2) {
            float* red = sm + OFF_RED + (slice-2)*2048;
            float2 a0 = up2(ua0), a1 = up2(ua1), a2 = up2(ua2), a3 = up2(ua3);
            float2 b0 = up2(oa0), b1 = up2(oa1), b2 = up2(oa2), b3 = up2(oa3);
            *(float4*)&red[c0*32 + vv]           = make_float4(a0.x,a0.y,a1.x,a1.y);
            *(float4*)&red[(c0+1)*32 + vv]       = make_float4(a2.x,a2.y,a3.x,a3.y);
            *(float4*)&red[1024 + c0*32 + vv]    = make_float4(b0.x,b0.y,b1.x,b1.y);
            *(float4*)&red[1024 + (c0+1)*32 + vv]= make_float4(b2.x,b2.y,b3.x,b3.y);
        }
        __syncthreads();

        // ---- issue WQ(t+1) prefetch now that phase-1 reads are done ----
        if (t + 1 < NCH) {
            const float4* wqsrc = (const float4*)(g_wq + bhoff2 + (long)(t+1)*(2*CHELEM));
            #pragma unroll
            for (int it = 0; it < 8; it++) {
                int idx = tid + it*512;
                cpa16(smb + OFF_WQ*4 + idx*16, wqsrc + idx);
            }
            CP_COMMIT();
        }

        // round A: slice 0 += RED[0] (slice2); slice 1 += RED[1] (slice3), then store to RED[1]
        if (slice < 2) {
            const float* red = sm + OFF_RED + slice*2048;
            float4 ru0 = *(const float4*)&red[c0*32 + vv];
            float4 ru1 = *(const float4*)&red[(c0+1)*32 + vv];
            float4 ro0 = *(const float4*)&red[1024 + c0*32 + vv];
            float4 ro1 = *(const float4*)&red[1024 + (c0+1)*32 + vv];
            fadd2(ua0, pk2(ru0.x,ru0.y)); fadd2(ua1, pk2(ru0.z,ru0.w));
            fadd2(ua2, pk2(ru1.x,ru1.y)); fadd2(ua3, pk2(ru1.z,ru1.w));
            fadd2(oa0, pk2(ro0.x,ro0.y)); fadd2(oa1, pk2(ro0.z,ro0.w));
            fadd2(oa2, pk2(ro1.x,ro1.y)); fadd2(oa3, pk2(ro1.z,ro1.w));
        }
        if (slice == 1) {
            float* red = sm + OFF_RED + 2048;
            float2 a0 = up2(ua0), a1 = up2(ua1), a2 = up2(ua2), a3 = up2(ua3);
            float2 b0 = up2(oa0), b1 = up2(oa1), b2 = up2(oa2), b3 = up2(oa3);
            *(float4*)&red[c0*32 + vv]           = make_float4(a0.x,a0.y,a1.x,a1.y);
            *(float4*)&red[(c0+1)*32 + vv]       = make_float4(a2.x,a2.y,a3.x,a3.y);
            *(float4*)&red[1024 + c0*32 + vv]    = make_float4(b0.x,b0.y,b1.x,b1.y);
            *(float4*)&red[1024 + (c0+1)*32 + vv]= make_float4(b2.x,b2.y,b3.x,b3.y);
        }
        __syncthreads();

        // round B: slice 0 adds RED[1] -> final; computes us = u_raw - u, po = o
        if (slice == 0) {
            const float* red = sm + OFF_RED + 2048;
            float4 ru0 = *(const float4*)&red[c0*32 + vv];
            float4 ru1 = *(const float4*)&red[(c0+1)*32 + vv];
            float4 ro0 = *(const float4*)&red[1024 + c0*32 + vv];
            float4 ro1 = *(const float4*)&red[1024 + (c0+1)*32 + vv];
            fadd2(ua0, pk2(ru0.x,ru0.y)); fadd2(ua1, pk2(ru0.z,ru0.w));
            fadd2(ua2, pk2(ru1.x,ru1.y)); fadd2(ua3, pk2(ru1.z,ru1.w));
            fadd2(oa0, pk2(ro0.x,ro0.y)); fadd2(oa1, pk2(ro0.z,ro0.w));
            fadd2(oa2, pk2(ro1.x,ro1.y)); fadd2(oa3, pk2(ro1.z,ro1.w));

            const float* ub = sm + OFF_U + bsel*1152;
            float4 ur0 = *(const float4*)&ub[c0*36 + vv];
            float4 ur1 = *(const float4*)&ub[(c0+1)*36 + vv];
            float2 u0 = up2(ua0), u1 = up2(ua1), u2 = up2(ua2), u3 = up2(ua3);
            *(float4*)&us[c0*36 + vv] =
                make_float4(ur0.x-u0.x, ur0.y-u0.y, ur0.z-u1.x, ur0.w-u1.y);
            *(float4*)&us[(c0+1)*36 + vv] =
                make_float4(ur1.x-u2.x, ur1.y-u2.y, ur1.z-u3.x, ur1.w-u3.y);
            float2 o0 = up2(oa0), o1 = up2(oa1), o2 = up2(oa2), o3 = up2(oa3);
            *(float4*)&po[c0*36 + vv]     = make_float4(o0.x,o0.y,o1.x,o1.y);
            *(float4*)&po[(c0+1)*36 + vv] = make_float4(o2.x,o2.y,o3.x,o3.y);
        }
        __syncthreads();

        // ==== phase 2: o = po + attn_local . u ====
        {
            const float* ab = sm + OFF_A + bsel*1152;
            float2 pv = *(const float2*)&po[c_p2*36 + v_p2];
            ull oacc = pk2(pv.x, pv.y);
            #pragma unroll 8
            for (int d = 0; d < 32; d++) {
                float2 u2 = *(const float2*)&us[d*36 + v_p2];
                float av = ab[c_p2*36 + d];
                ffma2(oacc, pk2(av, av), pk2(u2.x, u2.y));
            }
            float2 r = up2(oacc);
            *(float2*)(outp + ((long)bh*LSEQ + (long)t*CC + c_p2)*DV + v0 + v_p2) = r;
        }

        // ==== phase 3: S = gm*S + kn^T . u ====
        {
            const float* kb = sm + OFF_K + bsel*8192;
            ull acc0=0,acc1=0,acc2=0,acc3=0,acc4=0,acc5=0,acc6=0,acc7=0;
            #pragma unroll 4
            for (int c = 0; c < 32; c++) {
                float4 kv4 = *(const float4*)&kb[c*256 + kx3];
                float4 u4  = *(const float4*)&us[c*36 + vv3];
                ull u01 = pk2(u4.x, u4.y), u23 = pk2(u4.z, u4.w);
                ull p0 = pk2(kv4.x, kv4.x); ffma2(acc0, p0, u01); ffma2(acc1, p0, u23);
                ull p1 = pk2(kv4.y, kv4.y); ffma2(acc2, p1, u01); ffma2(acc3, p1, u23);
                ull p2 = pk2(kv4.z, kv4.z); ffma2(acc4, p2, u01); ffma2(acc5, p2, u23);
                ull p3 = pk2(kv4.w, kv4.w); ffma2(acc6, p3, u01); ffma2(acc7, p3, u23);
            }
            const float gm = g_gm[bh*NCH + t];
            const ull gmp = pk2(gm, gm);
            const bool last = (t == NCH-1);
            float* sfp = sFinal + (long)bh*DK*DV;
            #pragma unroll
            for (int r = 0; r < 4; r++) {
                const int row = kx3 + r;
                ulonglong2 so = *(const ulonglong2*)&Ss[row*36 + vv3];
                ull n0, n1;
                switch (r) {
                    case 0: n0 = acc0; n1 = acc1; break;
                    case 1: n0 = acc2; n1 = acc3; break;
                    case 2: n0 = acc4; n1 = acc5; break;
                    default: n0 = acc6; n1 = acc7; break;
                }
                ffma2(n0, so.x, gmp);
                ffma2(n1, so.y, gmp);
                ulonglong2 sn; sn.x = n0; sn.y = n1;
                *(ulonglong2*)&Ss[row*36 + vv3] = sn;
                if (last) *(ulonglong2*)&sfp[(long)row*DV + v0 + vv3] = sn;
            }
        }
        // loop-top __syncthreads orders phase-3 S writes vs next phase 1
    }
}

// ================= launch =================
extern "C" void kernel_launch(void* const* d_in, const int* in_sizes, int n_in,
                              void* d_out, int out_size) {
    const float* q     = (const float*)d_in[0];
    const float* k     = (const float*)d_in[1];
    const float* v     = (const float*)d_in[2];
    const float* beta  = (const float*)d_in[3];
    const float* gamma = (const float*)d_in[4];
    float* outp = (float*)d_out;
    float* sfin = outp + (long)BHn*LSEQ*DV;   // S appended after out

    cudaFuncSetAttribute(pre_kernel,  cudaFuncAttributeMaxDynamicSharedMemorySize,
                         PRE_SMEM_FLOATS*4);
    cudaFuncSetAttribute(scan_kernel, cudaFuncAttributeMaxDynamicSharedMemorySize,
                         SCAN_SMEM_FLOATS*4);
    (void)in_sizes; (void)n_in; (void)out_size;

    pre_kernel<<<BHn*NCH, 256, PRE_SMEM_FLOATS*4>>>(q, k, v, beta, gamma);
    scan_kernel<<<dim3(8, BHn), 512, SCAN_SMEM_FLOATS*4>>>(outp, sfin);
}

// round 6
// speedup vs baseline: 2.5627x; 1.1879x over previous
#include <cuda_runtime.h>
#include <cuda_bf16.h>
#include <cstdint>

// DeltaNet chunkwise delta-rule linear attention with decay.
// b=4 h=4 (BH=16), L=4096, dk=dv=256, chunk C=32, NCH=128 chunks.
//
//  pre_kernel  : per-chunk parallel precompute (2 CTAs/SM via launch_bounds).
//  scan_kernel : ONE persistent launch. 128 CTAs (16 bh x 8 v-blocks), 512 thr.
//                Operand prefetch via cp.async.bulk (TMA) + mbarrier -> near-zero
//                issue cost (was LDGSTS-issue-bound). Register-tiled f32x2 GEMMs.

#define BHn 16
#define LSEQ 4096
#define DK 256
#define DV 256
#define CC 32
#define NCH 128
#define CHELEM (CC*DK)          // 8192 floats per chunk per tensor

// -------- scratch (device globals; no allocation allowed) --------
__device__ float g_wq[BHn*NCH*2*CHELEM];   // [bh][ch][k][64]: {w[k,2c],w[k,2c+1],q[k,2c],q[k,2c+1]}
__device__ float g_kn[BHn*NCH*CHELEM];     // [bh][ch][c][k]  (c-major)
__device__ float g_u [BHn*8*NCH*CC*32];    // [bh][vblk][ch][c][32]  (CTA-contiguous slices)
__device__ float g_attn[BHn*NCH*CC*CC];    // [bh][ch][c][d] = attn (masked d<=c)
__device__ float g_gm[BHn*NCH];

// ---------- packed f32x2 helpers ----------
typedef unsigned long long ull;

__device__ __forceinline__ void ffma2(ull &d, ull a, ull b) {
    asm("fma.rn.f32x2 %0, %1, %2, %0;" : "+l"(d) : "l"(a), "l"(b));
}
__device__ __forceinline__ void fadd2(ull &d, ull a) {
    asm("add.rn.f32x2 %0, %0, %1;" : "+l"(d) : "l"(a));
}
__device__ __forceinline__ ull pk2(float a, float b) {
    ull r; asm("mov.b64 %0, {%1, %2};" : "=l"(r) : "f"(a), "f"(b)); return r;
}
__device__ __forceinline__ float2 up2(ull p) {
    float2 r; asm("mov.b64 {%0, %1}, %2;" : "=f"(r.x), "=f"(r.y) : "l"(p)); return r;
}
__device__ __forceinline__ uint32_t smem_u32(const void* p) {
    uint32_t a;
    asm("{ .reg .u64 t; cvta.to.shared.u64 t, %1; cvt.u32.u64 %0, t; }" : "=r"(a) : "l"(p));
    return a;
}
// ---------- bulk-copy + mbarrier ----------
__device__ __forceinline__ void bulkcp(uint32_t dst, const void* src, uint32_t bytes,
                                       uint32_t mbar) {
    asm volatile(
        "cp.async.bulk.shared::cluster.global.mbarrier::complete_tx::bytes [%0], [%1], %2, [%3];"
        :: "r"(dst), "l"(src), "r"(bytes), "r"(mbar) : "memory");
}
__device__ __forceinline__ void mbar_init(uint32_t mbar, uint32_t cnt) {
    asm volatile("mbarrier.init.shared.b64 [%0], %1;" :: "r"(mbar), "r"(cnt) : "memory");
}
__device__ __forceinline__ void mbar_expect(uint32_t mbar, uint32_t bytes) {
    asm volatile("mbarrier.arrive.expect_tx.shared.b64 _, [%0], %1;"
                 :: "r"(mbar), "r"(bytes) : "memory");
}
__device__ __forceinline__ void mbar_wait(uint32_t mbar, uint32_t parity) {
    uint32_t done;
    asm volatile(
        "{\n\t.reg .pred p;\n\t"
        "mbarrier.try_wait.parity.acquire.cta.shared::cta.b64 p, [%1], %2;\n\t"
        "selp.b32 %0, 1, 0, p;\n\t}"
        : "=r"(done) : "r"(mbar), "r"(parity) : "memory");
    if (!done) {
        asm volatile(
            "{\n\t.reg .pred P1;\n\t"
            "WAIT_LOOP_%=:\n\t"
            "mbarrier.try_wait.parity.acquire.cta.shared::cta.b64 P1, [%0], %1, 0x989680;\n\t"
            "@P1 bra.uni WAIT_DONE_%=;\n\t"
            "bra.uni WAIT_LOOP_%=;\n\t"
            "WAIT_DONE_%=:\n\t}"
            :: "r"(mbar), "r"(parity) : "memory");
    }
}

// ================= preprocess =================
#define PRE_SMEM_FLOATS (8320+8320+1056+32+32)

__global__ __launch_bounds__(256, 2)
void pre_kernel(const float* __restrict__ q, const float* __restrict__ k,
                const float* __restrict__ v, const float* __restrict__ beta,
                const float* __restrict__ gamma) {
    extern __shared__ float sm[];
    float* qs = sm;              // 32*260
    float* ks = sm + 8320;       // 32*260
    float* As = sm + 16640;      // 32*33
    float* bs = sm + 17696;      // 32
    float* gs = sm + 17728;      // 32

    const int tid  = threadIdx.x;
    const int lane = tid & 31;
    const int wid  = tid >> 5;
    const int bh = blockIdx.x >> 7;
    const int ch = blockIdx.x & 127;
    const long tok0 = (long)bh*LSEQ + (long)ch*CC;

    const float* qg = q + tok0*DK;
    const float* kg = k + tok0*DK;

    #pragma unroll 8
    for (int i = 0; i < 32; i++) {
        qs[i*260 + tid] = qg[i*DK + tid];
        ks[i*260 + tid] = kg[i*DK + tid];
    }
    if (tid < 32) { bs[tid] = beta[tok0 + tid]; gs[tid] = gamma[tok0 + tid]; }
    __syncthreads();

    // l2 normalize rows (warp per row)
    for (int r = wid; r < 32; r += 8) {
        float s = 0.f;
        #pragma unroll
        for (int x = lane; x < 256; x += 32) { float t = qs[r*260+x]; s += t*t; }
        s += __shfl_xor_sync(0xffffffffu, s, 16);
        s += __shfl_xor_sync(0xffffffffu, s, 8);
        s += __shfl_xor_sync(0xffffffffu, s, 4);
        s += __shfl_xor_sync(0xffffffffu, s, 2);
        s += __shfl_xor_sync(0xffffffffu, s, 1);
        float inv = rsqrtf(s + 1e-6f);
        #pragma unroll
        for (int x = lane; x < 256; x += 32) qs[r*260+x] *= inv;

        float s2 = 0.f;
        #pragma unroll
        for (int x = lane; x < 256; x += 32) { float t = ks[r*260+x]; s2 += t*t; }
        s2 += __shfl_xor_sync(0xffffffffu, s2, 16);
        s2 += __shfl_xor_sync(0xffffffffu, s2, 8);
        s2 += __shfl_xor_sync(0xffffffffu, s2, 4);
        s2 += __shfl_xor_sync(0xffffffffu, s2, 2);
        s2 += __shfl_xor_sync(0xffffffffu, s2, 1);
        float inv2 = rsqrtf(s2 + 1e-6f);
        #pragma unroll
        for (int x = lane; x < 256; x += 32) ks[r*260+x] *= inv2;
    }
    __syncthreads();

    const long cb = ((long)bh*NCH + ch)*CHELEM;

    // write kn (c-major, coalesced, unscaled)
    {
        float* knp = g_kn + cb;
        #pragma unroll 8
        for (int i = 0; i < 32; i++) knp[i*DK + tid] = ks[i*260 + tid];
    }

    // ---- Gram matrices: warp handles rows i0..i0+3, lanes give all j ----
    {
        float* atp = g_attn + ((long)bh*NCH + ch)*CC*CC;
        const int i0 = wid*4;
        float accA0=0,accA1=0,accA2=0,accA3=0;
        float accQ0=0,accQ1=0,accQ2=0,accQ3=0;
        #pragma unroll 4
        for (int k4 = 0; k4 < 64; k4++) {
            float4 kj = *(float4*)&ks[lane*260 + k4*4];           // scattered
            float4 ki0 = *(float4*)&ks[(i0+0)*260 + k4*4];        // broadcasts
            float4 qi0 = *(float4*)&qs[(i0+0)*260 + k4*4];
            accA0 += ki0.x*kj.x + ki0.y*kj.y + ki0.z*kj.z + ki0.w*kj.w;
            accQ0 += qi0.x*kj.x + qi0.y*kj.y + qi0.z*kj.z + qi0.w*kj.w;
            float4 ki1 = *(float4*)&ks[(i0+1)*260 + k4*4];
            float4 qi1 = *(float4*)&qs[(i0+1)*260 + k4*4];
            accA1 += ki1.x*kj.x + ki1.y*kj.y + ki1.z*kj.z + ki1.w*kj.w;
            accQ1 += qi1.x*kj.x + qi1.y*kj.y + qi1.z*kj.z + qi1.w*kj.w;
            float4 ki2 = *(float4*)&ks[(i0+2)*260 + k4*4];
            float4 qi2 = *(float4*)&qs[(i0+2)*260 + k4*4];
            accA2 += ki2.x*kj.x + ki2.y*kj.y + ki2.z*kj.z + ki2.w*kj.w;
            accQ2 += qi2.x*kj.x + qi2.y*kj.y + qi2.z*kj.z + qi2.w*kj.w;
            float4 ki3 = *(float4*)&ks[(i0+3)*260 + k4*4];
            float4 qi3 = *(float4*)&qs[(i0+3)*260 + k4*4];
            accA3 += ki3.x*kj.x + ki3.y*kj.y + ki3.z*kj.z + ki3.w*kj.w;
            accQ3 += qi3.x*kj.x + qi3.y*kj.y + qi3.z*kj.z + qi3.w*kj.w;
        }
        if (lane < i0+0) As[(i0+0)*33 + lane] = -bs[i0+0]*accA0;
        if (lane < i0+1) As[(i0+1)*33 + lane] = -bs[i0+1]*accA1;
        if (lane < i0+2) As[(i0+2)*33 + lane] = -bs[i0+2]*accA2;
        if (lane < i0+3) As[(i0+3)*33 + lane] = -bs[i0+3]*accA3;
        atp[(i0+0)*32 + lane] = (lane <= i0+0) ? accQ0 : 0.0f;
        atp[(i0+1)*32 + lane] = (lane <= i0+1) ? accQ1 : 0.0f;
        atp[(i0+2)*32 + lane] = (lane <= i0+2) ? accQ2 : 0.0f;
        atp[(i0+3)*32 + lane] = (lane <= i0+3) ? accQ3 : 0.0f;
    }
    __syncthreads();

    // forward substitution (warp 0): strict-lower T in As
    if (wid == 0) {
        int col = lane;
        for (int i = 1; i < 32; i++) {
            float inc = 0.f;
            if (col < i) {
                for (int j = col+1; j < i; j++) inc += As[i*33+j]*As[j*33+col];
            }
            __syncwarp();
            if (col < i) As[i*33+col] += inc;
            __syncwarp();
        }
    }
    if (wid == 1) {
        float g2 = gs[lane];
        g2 += __shfl_xor_sync(0xffffffffu, g2, 16);
        g2 += __shfl_xor_sync(0xffffffffu, g2, 8);
        g2 += __shfl_xor_sync(0xffffffffu, g2, 4);
        g2 += __shfl_xor_sync(0xffffffffu, g2, 2);
        g2 += __shfl_xor_sync(0xffffffffu, g2, 1);
        if (lane == 0) g_gm[bh*NCH + ch] = g2 * (1.0f/32.0f);
    }
    __syncthreads();

    // scale ks in place by beta (each thread touches only its own column)
    #pragma unroll
    for (int j = 0; j < 32; j++) ks[j*260 + tid] *= bs[j];

    // ---- fused T-apply: u_raw = T(beta*v), w = T(beta*kn) ----
    {
        float colv[32];
        const float* vg = v + tok0*DV;
        #pragma unroll
        for (int j = 0; j < 32; j++) colv[j] = vg[j*DV + tid] * bs[j];

        // u slice layout: [bh][vblk=tid>>5][ch][c][32]
        float* up = g_u + (((long)(bh*8 + (tid>>5))*NCH + ch))*CC*32 + (tid & 31);
        float wout[32];
        #pragma unroll
        for (int i = 0; i < 32; i++) {
            float accV = colv[i];
            float accK = ks[i*260 + tid];
            #pragma unroll
            for (int j = 0; j < i; j++) {
                float a = As[i*33+j];
                accV += a*colv[j];
                accK += a*ks[j*260 + tid];
            }
            up[i*32] = accV;
            wout[i] = accK;
        }
        // interleaved WQ write: row k=tid, 64 floats {w0,w1,q0,q1}x16
        float* wqp = g_wq + ((long)bh*NCH + ch)*(2*CHELEM) + (long)tid*64;
        #pragma unroll
        for (int cp = 0; cp < 16; cp++) {
            *(float4*)&wqp[cp*4] = make_float4(wout[2*cp], wout[2*cp+1],
                                               qs[(2*cp)*260 + tid], qs[(2*cp+1)*260 + tid]);
        }
    }
}

// ================= persistent scan (512 threads, bulk-copy prefetch) =================
// smem float layout:
#define OFF_S   0        // [256][36]      9216
#define OFF_WQ  9216     // [256][64]      16384 (single buffer, fused W+Q)
#define OFF_K   25600    // [2][32][256]   16384
#define OFF_U   41984    // [2][32][32]    2048
#define OFF_A   44032    // [2][32][32]    2048
#define OFF_RED 46080    // [2][2048]      4096
#define OFF_US  50176    // [32][36]       1152
#define OFF_PO  51328    // [32][36]       1152
#define OFF_MB  52480    // mbarrier (8B)
#define SCAN_SMEM_FLOATS 52496   // 209984 bytes

#define CHUNK_BYTES (65536u + 32768u + 4096u + 4096u)   // WQ + K + U + A = 106496

__global__ __launch_bounds__(512, 1)
void scan_kernel(float* __restrict__ outp, float* __restrict__ sFinal) {
    extern __shared__ float sm[];
    const uint32_t smb = smem_u32(sm);
    const uint32_t mbar = smb + OFF_MB*4;

    const int tid  = threadIdx.x;
    const int bh = blockIdx.y;
    const int v0 = blockIdx.x * 32;

    float* Ss = sm + OFF_S;
    float* us = sm + OFF_US;
    float* po = sm + OFF_PO;

    const long bhoff  = (long)bh*NCH*CHELEM;
    const long bhoff2 = (long)bh*NCH*(2*CHELEM);
    const long ubase  = ((long)(bh*8 + blockIdx.x))*NCH*CC*32;

    // phase-1 mapping: 4 k-slices x 128 threads; thread tile 2c x 4v
    const int slice = tid >> 7;
    const int t128  = tid & 127;
    const int cp2   = t128 >> 3;       // 0..15 -> c = cp2*2
    const int vp    = t128 & 7;        // v = vp*4
    const int c0    = cp2*2;
    const int vv    = vp*4;

    // phase-2 mapping: 1c x 2v
    const int c_p2 = tid >> 4;         // 0..31
    const int v_p2 = (tid & 15)*2;

    // phase-3 mapping: 4k x 4v
    const int kx3 = (tid >> 3)*4;
    const int vv3 = (tid & 7)*4;

    // zero resident S slice
    #pragma unroll
    for (int i = 0; i < 18; i++) Ss[tid + i*512] = 0.0f;

    // init mbarrier + fence, then issue chunk-0 prefetch (all via bulk copies)
    if (tid == 0) mbar_init(mbar, 1);
    asm volatile("fence.proxy.async.shared::cta;" ::: "memory");
    __syncthreads();
    if (tid == 0) {
        mbar_expect(mbar, CHUNK_BYTES);
        bulkcp(smb + OFF_WQ*4, g_wq + bhoff2, 65536u, mbar);
        bulkcp(smb + OFF_K*4,  g_kn + bhoff,  32768u, mbar);
        bulkcp(smb + OFF_U*4,  g_u + ubase,   4096u,  mbar);
        bulkcp(smb + OFF_A*4,  g_attn + (long)bh*NCH*CC*CC, 4096u, mbar);
    }

    for (int t = 0; t < NCH; t++) {
        mbar_wait(mbar, t & 1);
        __syncthreads();   // chunk-t operands visible to all; S(t-1) update visible

        const int bsel = t & 1;

        // ---- issue K/U/A(t+1) prefetch (double-buffered); WQ issued after phase 1 ----
        if (tid == 0 && t + 1 < NCH) {
            const int tn = t + 1, nb = tn & 1;
            mbar_expect(mbar, CHUNK_BYTES);
            bulkcp(smb + (OFF_K + nb*8192)*4, g_kn + bhoff + (long)tn*CHELEM, 32768u, mbar);
            bulkcp(smb + (OFF_U + nb*1024)*4, g_u + ubase + (long)tn*CC*32,   4096u,  mbar);
            bulkcp(smb + (OFF_A + nb*1024)*4, g_attn + ((long)bh*NCH + tn)*CC*CC, 4096u, mbar);
        }

        const float* wqb = sm + OFF_WQ;

        // ==== phase 1: u = W.S, o = Q.S  (k-sliced register tiles, fused WQ read) ====
        ull ua0=0,ua1=0,ua2=0,ua3=0, oa0=0,oa1=0,oa2=0,oa3=0;
        {
            const int kbase = slice*64;
            #pragma unroll 8
            for (int kk = 0; kk < 64; kk++) {
                const int k = kbase + kk;
                float4 s4 = *(const float4*)&Ss[k*36 + vv];
                ull s01 = pk2(s4.x, s4.y), s23 = pk2(s4.z, s4.w);
                float4 wq = *(const float4*)&wqb[k*64 + cp2*4];
                ull wx = pk2(wq.x, wq.x);
                ffma2(ua0, wx, s01); ffma2(ua1, wx, s23);
                ull wy = pk2(wq.y, wq.y);
                ffma2(ua2, wy, s01); ffma2(ua3, wy, s23);
                ull qx = pk2(wq.z, wq.z);
                ffma2(oa0, qx, s01); ffma2(oa1, qx, s23);
                ull qy = pk2(wq.w, wq.w);
                ffma2(oa2, qy, s01); ffma2(oa3, qy, s23);
            }
        }
        // slices 2,3 publish partials
        if (slice >= 2) {
            float* red = sm + OFF_RED + (slice-2)*2048;
            float2 a0 = up2(ua0), a1 = up2(ua1), a2 = up2(ua2), a3 = up2(ua3);
            float2 b0 = up2(oa0), b1 = up2(oa1), b2 = up2(oa2), b3 = up2(oa3);
            *(float4*)&red[c0*32 + vv]           = make_float4(a0.x,a0.y,a1.x,a1.y);
            *(float4*)&red[(c0+1)*32 + vv]       = make_float4(a2.x,a2.y,a3.x,a3.y);
            *(float4*)&red[1024 + c0*32 + vv]    = make_float4(b0.x,b0.y,b1.x,b1.y);
            *(float4*)&red[1024 + (c0+1)*32 + vv]= make_float4(b2.x,b2.y,b3.x,b3.y);
        }
        __syncthreads();

        // ---- WQ(t+1) bulk now that phase-1 reads are done ----
        if (tid == 0 && t + 1 < NCH) {
            bulkcp(smb + OFF_WQ*4, g_wq + bhoff2 + (long)(t+1)*(2*CHELEM), 65536u, mbar);
        }

        // round A
        if (slice < 2) {
            const float* red = sm + OFF_RED + slice*2048;
            float4 ru0 = *(const float4*)&red[c0*32 + vv];
            float4 ru1 = *(const float4*)&red[(c0+1)*32 + vv];
            float4 ro0 = *(const float4*)&red[1024 + c0*32 + vv];
            float4 ro1 = *(const float4*)&red[1024 + (c0+1)*32 + vv];
            fadd2(ua0, pk2(ru0.x,ru0.y)); fadd2(ua1, pk2(ru0.z,ru0.w));
            fadd2(ua2, pk2(ru1.x,ru1.y)); fadd2(ua3, pk2(ru1.z,ru1.w));
            fadd2(oa0, pk2(ro0.x,ro0.y)); fadd2(oa1, pk2(ro0.z,ro0.w));
            fadd2(oa2, pk2(ro1.x,ro1.y)); fadd2(oa3, pk2(ro1.z,ro1.w));
        }
        if (slice == 1) {
            float* red = sm + OFF_RED + 2048;
            float2 a0 = up2(ua0), a1 = up2(ua1), a2 = up2(ua2), a3 = up2(ua3);
            float2 b0 = up2(oa0), b1 = up2(oa1), b2 = up2(oa2), b3 = up2(oa3);
            *(float4*)&red[c0*32 + vv]           = make_float4(a0.x,a0.y,a1.x,a1.y);
            *(float4*)&red[(c0+1)*32 + vv]       = make_float4(a2.x,a2.y,a3.x,a3.y);
            *(float4*)&red[1024 + c0*32 + vv]    = make_float4(b0.x,b0.y,b1.x,b1.y);
            *(float4*)&red[1024 + (c0+1)*32 + vv]= make_float4(b2.x,b2.y,b3.x,b3.y);
        }
        __syncthreads();

        // round B: slice 0 finalizes; computes us = u_raw - u, po = o
        if (slice == 0) {
            const float* red = sm + OFF_RED + 2048;
            float4 ru0 = *(const float4*)&red[c0*32 + vv];
            float4 ru1 = *(const float4*)&red[(c0+1)*32 + vv];
            float4 ro0 = *(const float4*)&red[1024 + c0*32 + vv];
            float4 ro1 = *(const float4*)&red[1024 + (c0+1)*32 + vv];
            fadd2(ua0, pk2(ru0.x,ru0.y)); fadd2(ua1, pk2(ru0.z,ru0.w));
            fadd2(ua2, pk2(ru1.x,ru1.y)); fadd2(ua3, pk2(ru1.z,ru1.w));
            fadd2(oa0, pk2(ro0.x,ro0.y)); fadd2(oa1, pk2(ro0.z,ro0.w));
            fadd2(oa2, pk2(ro1.x,ro1.y)); fadd2(oa3, pk2(ro1.z,ro1.w));

            const float* ub = sm + OFF_U + bsel*1024;
            float4 ur0 = *(const float4*)&ub[c0*32 + vv];
            float4 ur1 = *(const float4*)&ub[(c0+1)*32 + vv];
            float2 u0 = up2(ua0), u1 = up2(ua1), u2 = up2(ua2), u3 = up2(ua3);
            *(float4*)&us[c0*36 + vv] =
                make_float4(ur0.x-u0.x, ur0.y-u0.y, ur0.z-u1.x, ur0.w-u1.y);
            *(float4*)&us[(c0+1)*36 + vv] =
                make_float4(ur1.x-u2.x, ur1.y-u2.y, ur1.z-u3.x, ur1.w-u3.y);
            float2 o0 = up2(oa0), o1 = up2(oa1), o2 = up2(oa2), o3 = up2(oa3);
            *(float4*)&po[c0*36 + vv]     = make_float4(o0.x,o0.y,o1.x,o1.y);
            *(float4*)&po[(c0+1)*36 + vv] = make_float4(o2.x,o2.y,o3.x,o3.y);
        }
        __syncthreads();

        // ==== phase 2: o = po + attn_local . u  (triangular: d <= c) ====
        {
            const float* ab = sm + OFF_A + bsel*1024;
            float2 pv = *(const float2*)&po[c_p2*36 + v_p2];
            ull oacc = pk2(pv.x, pv.y);
            #pragma unroll 4
            for (int d = 0; d <= c_p2; d++) {
                float2 u2 = *(const float2*)&us[d*36 + v_p2];
                float av = ab[c_p2*32 + d];
                ffma2(oacc, pk2(av, av), pk2(u2.x, u2.y));
            }
            float2 r = up2(oacc);
            *(float2*)(outp + ((long)bh*LSEQ + (long)t*CC + c_p2)*DV + v0 + v_p2) = r;
        }

        // ==== phase 3: S = gm*S + kn^T . u ====
        {
            const float* kb = sm + OFF_K + bsel*8192;
            ull acc0=0,acc1=0,acc2=0,acc3=0,acc4=0,acc5=0,acc6=0,acc7=0;
            #pragma unroll 4
            for (int c = 0; c < 32; c++) {
                float4 kv4 = *(const float4*)&kb[c*256 + kx3];
                float4 u4  = *(const float4*)&us[c*36 + vv3];
                ull u01 = pk2(u4.x, u4.y), u23 = pk2(u4.z, u4.w);
                ull p0 = pk2(kv4.x, kv4.x); ffma2(acc0, p0, u01); ffma2(acc1, p0, u23);
                ull p1 = pk2(kv4.y, kv4.y); ffma2(acc2, p1, u01); ffma2(acc3, p1, u23);
                ull p2 = pk2(kv4.z, kv4.z); ffma2(acc4, p2, u01); ffma2(acc5, p2, u23);
                ull p3 = pk2(kv4.w, kv4.w); ffma2(acc6, p3, u01); ffma2(acc7, p3, u23);
            }
            const float gm = g_gm[bh*NCH + t];
            const ull gmp = pk2(gm, gm);
            const bool last = (t == NCH-1);
            float* sfp = sFinal + (long)bh*DK*DV;
            #pragma unroll
            for (int r = 0; r < 4; r++) {
                const int row = kx3 + r;
                ulonglong2 so = *(const ulonglong2*)&Ss[row*36 + vv3];
                ull n0, n1;
                switch (r) {
                    case 0: n0 = acc0; n1 = acc1; break;
                    case 1: n0 = acc2; n1 = acc3; break;
                    case 2: n0 = acc4; n1 = acc5; break;
                    default: n0 = acc6; n1 = acc7; break;
                }
                ffma2(n0, so.x, gmp);
                ffma2(n1, so.y, gmp);
                ulonglong2 sn; sn.x = n0; sn.y = n1;
                *(ulonglong2*)&Ss[row*36 + vv3] = sn;
                if (last) *(ulonglong2*)&sfp[(long)row*DV + v0 + vv3] = sn;
            }
        }
        // loop-top barrier orders phase-3 S writes vs next phase 1
    }
}

// ================= launch =================
extern "C" void kernel_launch(void* const* d_in, const int* in_sizes, int n_in,
                              void* d_out, int out_size) {
    const float* q     = (const float*)d_in[0];
    const float* k     = (const float*)d_in[1];
    const float* v     = (const float*)d_in[2];
    const float* beta  = (const float*)d_in[3];
    const float* gamma = (const float*)d_in[4];
    float* outp = (float*)d_out;
    float* sfin = outp + (long)BHn*LSEQ*DV;   // S appended after out

    cudaFuncSetAttribute(pre_kernel,  cudaFuncAttributeMaxDynamicSharedMemorySize,
                         PRE_SMEM_FLOATS*4);
    cudaFuncSetAttribute(scan_kernel, cudaFuncAttributeMaxDynamicSharedMemorySize,
                         SCAN_SMEM_FLOATS*4);
    (void)in_sizes; (void)n_in; (void)out_size;

    pre_kernel<<<BHn*NCH, 256, PRE_SMEM_FLOATS*4>>>(q, k, v, beta, gamma);
    scan_kernel<<<dim3(8, BHn), 512, SCAN_SMEM_FLOATS*4>>>(outp, sfin);
}

// round 7
// speedup vs baseline: 2.5629x; 1.0001x over previous
#include <cuda_runtime.h>
#include <cuda_bf16.h>
#include <cstdint>

// DeltaNet chunkwise delta-rule linear attention with decay.
// b=4 h=4 (BH=16), L=4096, dk=dv=256, chunk C=32, NCH=128 chunks.
//
//  pre_kernel  : per-chunk parallel precompute (2 CTAs/SM via launch_bounds).
//  scan_kernel : ONE persistent launch. 128 CTAs (16 bh x 8 v-blocks), 512 thr.
//                Operand prefetch via cp.async.bulk (TMA) + mbarrier -> near-zero
//                issue cost (was LDGSTS-issue-bound). Register-tiled f32x2 GEMMs.

#define BHn 16
#define LSEQ 4096
#define DK 256
#define DV 256
#define CC 32
#define NCH 128
#define CHELEM (CC*DK)          // 8192 floats per chunk per tensor

// -------- scratch (device globals; no allocation allowed) --------
__device__ float g_wq[BHn*NCH*2*CHELEM];   // [bh][ch][k][64]: {w[k,2c],w[k,2c+1],q[k,2c],q[k,2c+1]}
__device__ float g_kn[BHn*NCH*CHELEM];     // [bh][ch][c][k]  (c-major)
__device__ float g_u [BHn*8*NCH*CC*32];    // [bh][vblk][ch][c][32]  (CTA-contiguous slices)
__device__ float g_attn[BHn*NCH*CC*CC];    // [bh][ch][c][d] = attn (masked d<=c)
__device__ float g_gm[BHn*NCH];

// ---------- packed f32x2 helpers ----------
typedef unsigned long long ull;

__device__ __forceinline__ void ffma2(ull &d, ull a, ull b) {
    asm("fma.rn.f32x2 %0, %1, %2, %0;" : "+l"(d) : "l"(a), "l"(b));
}
__device__ __forceinline__ void fadd2(ull &d, ull a) {
    asm("add.rn.f32x2 %0, %0, %1;" : "+l"(d) : "l"(a));
}
__device__ __forceinline__ ull pk2(float a, float b) {
    ull r; asm("mov.b64 %0, {%1, %2};" : "=l"(r) : "f"(a), "f"(b)); return r;
}
__device__ __forceinline__ float2 up2(ull p) {
    float2 r; asm("mov.b64 {%0, %1}, %2;" : "=f"(r.x), "=f"(r.y) : "l"(p)); return r;
}
__device__ __forceinline__ uint32_t smem_u32(const void* p) {
    uint32_t a;
    asm("{ .reg .u64 t; cvta.to.shared.u64 t, %1; cvt.u32.u64 %0, t; }" : "=r"(a) : "l"(p));
    return a;
}
// ---------- bulk-copy + mbarrier ----------
__device__ __forceinline__ void bulkcp(uint32_t dst, const void* src, uint32_t bytes,
                                       uint32_t mbar) {
    asm volatile(
        "cp.async.bulk.shared::cluster.global.mbarrier::complete_tx::bytes [%0], [%1], %2, [%3];"
        :: "r"(dst), "l"(src), "r"(bytes), "r"(mbar) : "memory");
}
__device__ __forceinline__ void mbar_init(uint32_t mbar, uint32_t cnt) {
    asm volatile("mbarrier.init.shared.b64 [%0], %1;" :: "r"(mbar), "r"(cnt) : "memory");
}
__device__ __forceinline__ void mbar_expect(uint32_t mbar, uint32_t bytes) {
    asm volatile("mbarrier.arrive.expect_tx.shared.b64 _, [%0], %1;"
                 :: "r"(mbar), "r"(bytes) : "memory");
}
__device__ __forceinline__ void mbar_wait(uint32_t mbar, uint32_t parity) {
    uint32_t done;
    asm volatile(
        "{\n\t.reg .pred p;\n\t"
        "mbarrier.try_wait.parity.acquire.cta.shared::cta.b64 p, [%1], %2;\n\t"
        "selp.b32 %0, 1, 0, p;\n\t}"
        : "=r"(done) : "r"(mbar), "r"(parity) : "memory");
    if (!done) {
        asm volatile(
            "{\n\t.reg .pred P1;\n\t"
            "WAIT_LOOP_%=:\n\t"
            "mbarrier.try_wait.parity.acquire.cta.shared::cta.b64 P1, [%0], %1, 0x989680;\n\t"
            "@P1 bra.uni WAIT_DONE_%=;\n\t"
            "bra.uni WAIT_LOOP_%=;\n\t"
            "WAIT_DONE_%=:\n\t}"
            :: "r"(mbar), "r"(parity) : "memory");
    }
}

// ================= preprocess =================
#define PRE_SMEM_FLOATS (8320+8320+1056+32+32)

__global__ __launch_bounds__(256, 2)
void pre_kernel(const float* __restrict__ q, const float* __restrict__ k,
                const float* __restrict__ v, const float* __restrict__ beta,
                const float* __restrict__ gamma) {
    extern __shared__ float sm[];
    float* qs = sm;              // 32*260
    float* ks = sm + 8320;       // 32*260
    float* As = sm + 16640;      // 32*33
    float* bs = sm + 17696;      // 32
    float* gs = sm + 17728;      // 32

    const int tid  = threadIdx.x;
    const int lane = tid & 31;
    const int wid  = tid >> 5;
    const int bh = blockIdx.x >> 7;
    const int ch = blockIdx.x & 127;
    const long tok0 = (long)bh*LSEQ + (long)ch*CC;

    const float* qg = q + tok0*DK;
    const float* kg = k + tok0*DK;

    #pragma unroll 8
    for (int i = 0; i < 32; i++) {
        qs[i*260 + tid] = qg[i*DK + tid];
        ks[i*260 + tid] = kg[i*DK + tid];
    }
    if (tid < 32) { bs[tid] = beta[tok0 + tid]; gs[tid] = gamma[tok0 + tid]; }
    __syncthreads();

    // l2 normalize rows (warp per row)
    for (int r = wid; r < 32; r += 8) {
        float s = 0.f;
        #pragma unroll
        for (int x = lane; x < 256; x += 32) { float t = qs[r*260+x]; s += t*t; }
        s += __shfl_xor_sync(0xffffffffu, s, 16);
        s += __shfl_xor_sync(0xffffffffu, s, 8);
        s += __shfl_xor_sync(0xffffffffu, s, 4);
        s += __shfl_xor_sync(0xffffffffu, s, 2);
        s += __shfl_xor_sync(0xffffffffu, s, 1);
        float inv = rsqrtf(s + 1e-6f);
        #pragma unroll
        for (int x = lane; x < 256; x += 32) qs[r*260+x] *= inv;

        float s2 = 0.f;
        #pragma unroll
        for (int x = lane; x < 256; x += 32) { float t = ks[r*260+x]; s2 += t*t; }
        s2 += __shfl_xor_sync(0xffffffffu, s2, 16);
        s2 += __shfl_xor_sync(0xffffffffu, s2, 8);
        s2 += __shfl_xor_sync(0xffffffffu, s2, 4);
        s2 += __shfl_xor_sync(0xffffffffu, s2, 2);
        s2 += __shfl_xor_sync(0xffffffffu, s2, 1);
        float inv2 = rsqrtf(s2 + 1e-6f);
        #pragma unroll
        for (int x = lane; x < 256; x += 32) ks[r*260+x] *= inv2;
    }
    __syncthreads();

    const long cb = ((long)bh*NCH + ch)*CHELEM;

    // write kn (c-major, coalesced, unscaled)
    {
        float* knp = g_kn + cb;
        #pragma unroll 8
        for (int i = 0; i < 32; i++) knp[i*DK + tid] = ks[i*260 + tid];
    }

    // ---- Gram matrices: warp handles rows i0..i0+3, lanes give all j ----
    {
        float* atp = g_attn + ((long)bh*NCH + ch)*CC*CC;
        const int i0 = wid*4;
        float accA0=0,accA1=0,accA2=0,accA3=0;
        float accQ0=0,accQ1=0,accQ2=0,accQ3=0;
        #pragma unroll 4
        for (int k4 = 0; k4 < 64; k4++) {
            float4 kj = *(float4*)&ks[lane*260 + k4*4];           // scattered
            float4 ki0 = *(float4*)&ks[(i0+0)*260 + k4*4];        // broadcasts
            float4 qi0 = *(float4*)&qs[(i0+0)*260 + k4*4];
            accA0 += ki0.x*kj.x + ki0.y*kj.y + ki0.z*kj.z + ki0.w*kj.w;
            accQ0 += qi0.x*kj.x + qi0.y*kj.y + qi0.z*kj.z + qi0.w*kj.w;
            float4 ki1 = *(float4*)&ks[(i0+1)*260 + k4*4];
            float4 qi1 = *(float4*)&qs[(i0+1)*260 + k4*4];
            accA1 += ki1.x*kj.x + ki1.y*kj.y + ki1.z*kj.z + ki1.w*kj.w;
            accQ1 += qi1.x*kj.x + qi1.y*kj.y + qi1.z*kj.z + qi1.w*kj.w;
            float4 ki2 = *(float4*)&ks[(i0+2)*260 + k4*4];
            float4 qi2 = *(float4*)&qs[(i0+2)*260 + k4*4];
            accA2 += ki2.x*kj.x + ki2.y*kj.y + ki2.z*kj.z + ki2.w*kj.w;
            accQ2 += qi2.x*kj.x + qi2.y*kj.y + qi2.z*kj.z + qi2.w*kj.w;
            float4 ki3 = *(float4*)&ks[(i0+3)*260 + k4*4];
            float4 qi3 = *(float4*)&qs[(i0+3)*260 + k4*4];
            accA3 += ki3.x*kj.x + ki3.y*kj.y + ki3.z*kj.z + ki3.w*kj.w;
            accQ3 += qi3.x*kj.x + qi3.y*kj.y + qi3.z*kj.z + qi3.w*kj.w;
        }
        if (lane < i0+0) As[(i0+0)*33 + lane] = -bs[i0+0]*accA0;
        if (lane < i0+1) As[(i0+1)*33 + lane] = -bs[i0+1]*accA1;
        if (lane < i0+2) As[(i0+2)*33 + lane] = -bs[i0+2]*accA2;
        if (lane < i0+3) As[(i0+3)*33 + lane] = -bs[i0+3]*accA3;
        atp[(i0+0)*32 + lane] = (lane <= i0+0) ? accQ0 : 0.0f;
        atp[(i0+1)*32 + lane] = (lane <= i0+1) ? accQ1 : 0.0f;
        atp[(i0+2)*32 + lane] = (lane <= i0+2) ? accQ2 : 0.0f;
        atp[(i0+3)*32 + lane] = (lane <= i0+3) ? accQ3 : 0.0f;
    }
    __syncthreads();

    // forward substitution (warp 0): strict-lower T in As
    if (wid == 0) {
        int col = lane;
        for (int i = 1; i < 32; i++) {
            float inc = 0.f;
            if (col < i) {
                for (int j = col+1; j < i; j++) inc += As[i*33+j]*As[j*33+col];
            }
            __syncwarp();
            if (col < i) As[i*33+col] += inc;
            __syncwarp();
        }
    }
    if (wid == 1) {
        float g2 = gs[lane];
        g2 += __shfl_xor_sync(0xffffffffu, g2, 16);
        g2 += __shfl_xor_sync(0xffffffffu, g2, 8);
        g2 += __shfl_xor_sync(0xffffffffu, g2, 4);
        g2 += __shfl_xor_sync(0xffffffffu, g2, 2);
        g2 += __shfl_xor_sync(0xffffffffu, g2, 1);
        if (lane == 0) g_gm[bh*NCH + ch] = g2 * (1.0f/32.0f);
    }
    __syncthreads();

    // scale ks in place by beta (each thread touches only its own column)
    #pragma unroll
    for (int j = 0; j < 32; j++) ks[j*260 + tid] *= bs[j];

    // ---- fused T-apply: u_raw = T(beta*v), w = T(beta*kn) ----
    {
        float colv[32];
        const float* vg = v + tok0*DV;
        #pragma unroll
        for (int j = 0; j < 32; j++) colv[j] = vg[j*DV + tid] * bs[j];

        // u slice layout: [bh][vblk=tid>>5][ch][c][32]
        float* up = g_u + (((long)(bh*8 + (tid>>5))*NCH + ch))*CC*32 + (tid & 31);
        float wout[32];
        #pragma unroll
        for (int i = 0; i < 32; i++) {
            float accV = colv[i];
            float accK = ks[i*260 + tid];
            #pragma unroll
            for (int j = 0; j < i; j++) {
                float a = As[i*33+j];
                accV += a*colv[j];
                accK += a*ks[j*260 + tid];
            }
            up[i*32] = accV;
            wout[i] = accK;
        }
        // interleaved WQ write: row k=tid, 64 floats {w0,w1,q0,q1}x16
        float* wqp = g_wq + ((long)bh*NCH + ch)*(2*CHELEM) + (long)tid*64;
        #pragma unroll
        for (int cp = 0; cp < 16; cp++) {
            *(float4*)&wqp[cp*4] = make_float4(wout[2*cp], wout[2*cp+1],
                                               qs[(2*cp)*260 + tid], qs[(2*cp+1)*260 + tid]);
        }
    }
}

// ================= persistent scan (512 threads, bulk-copy prefetch) =================
// smem float layout:
#define OFF_S   0        // [256][36]      9216
#define OFF_WQ  9216     // [256][64]      16384 (single buffer, fused W+Q)
#define OFF_K   25600    // [2][32][256]   16384
#define OFF_U   41984    // [2][32][32]    2048
#define OFF_A   44032    // [2][32][32]    2048
#define OFF_RED 46080    // [2][2048]      4096
#define OFF_US  50176    // [32][36]       1152
#define OFF_PO  51328    // [32][36]       1152
#define OFF_MB  52480    // mbarrier (8B)
#define SCAN_SMEM_FLOATS 52496   // 209984 bytes

#define CHUNK_BYTES (65536u + 32768u + 4096u + 4096u)   // WQ + K + U + A = 106496

__global__ __launch_bounds__(512, 1)
void scan_kernel(float* __restrict__ outp, float* __restrict__ sFinal) {
    extern __shared__ float sm[];
    const uint32_t smb = smem_u32(sm);
    const uint32_t mbar = smb + OFF_MB*4;

    const int tid  = threadIdx.x;
    const int bh = blockIdx.y;
    const int v0 = blockIdx.x * 32;

    float* Ss = sm + OFF_S;
    float* us = sm + OFF_US;
    float* po = sm + OFF_PO;

    const long bhoff  = (long)bh*NCH*CHELEM;
    const long bhoff2 = (long)bh*NCH*(2*CHELEM);
    const long ubase  = ((long)(bh*8 + blockIdx.x))*NCH*CC*32;

    // phase-1 mapping: 4 k-slices x 128 threads; thread tile 2c x 4v
    const int slice = tid >> 7;
    const int t128  = tid & 127;
    const int cp2   = t128 >> 3;       // 0..15 -> c = cp2*2
    const int vp    = t128 & 7;        // v = vp*4
    const int c0    = cp2*2;
    const int vv    = vp*4;

    // phase-2 mapping: 1c x 2v
    const int c_p2 = tid >> 4;         // 0..31
    const int v_p2 = (tid & 15)*2;

    // phase-3 mapping: 4k x 4v
    const int kx3 = (tid >> 3)*4;
    const int vv3 = (tid & 7)*4;

    // zero resident S slice
    #pragma unroll
    for (int i = 0; i < 18; i++) Ss[tid + i*512] = 0.0f;

    // init mbarrier + fence, then issue chunk-0 prefetch (all via bulk copies)
    if (tid == 0) mbar_init(mbar, 1);
    asm volatile("fence.proxy.async.shared::cta;" ::: "memory");
    __syncthreads();
    if (tid == 0) {
        mbar_expect(mbar, CHUNK_BYTES);
        bulkcp(smb + OFF_WQ*4, g_wq + bhoff2, 65536u, mbar);
        bulkcp(smb + OFF_K*4,  g_kn + bhoff,  32768u, mbar);
        bulkcp(smb + OFF_U*4,  g_u + ubase,   4096u,  mbar);
        bulkcp(smb + OFF_A*4,  g_attn + (long)bh*NCH*CC*CC, 4096u, mbar);
    }

    for (int t = 0; t < NCH; t++) {
        mbar_wait(mbar, t & 1);
        __syncthreads();   // chunk-t operands visible to all; S(t-1) update visible

        const int bsel = t & 1;

        // ---- issue K/U/A(t+1) prefetch (double-buffered); WQ issued after phase 1 ----
        if (tid == 0 && t + 1 < NCH) {
            const int tn = t + 1, nb = tn & 1;
            mbar_expect(mbar, CHUNK_BYTES);
            bulkcp(smb + (OFF_K + nb*8192)*4, g_kn + bhoff + (long)tn*CHELEM, 32768u, mbar);
            bulkcp(smb + (OFF_U + nb*1024)*4, g_u + ubase + (long)tn*CC*32,   4096u,  mbar);
            bulkcp(smb + (OFF_A + nb*1024)*4, g_attn + ((long)bh*NCH + tn)*CC*CC, 4096u, mbar);
        }

        const float* wqb = sm + OFF_WQ;

        // ==== phase 1: u = W.S, o = Q.S  (k-sliced register tiles, fused WQ read) ====
        ull ua0=0,ua1=0,ua2=0,ua3=0, oa0=0,oa1=0,oa2=0,oa3=0;
        {
            const int kbase = slice*64;
            #pragma unroll 8
            for (int kk = 0; kk < 64; kk++) {
                const int k = kbase + kk;
                float4 s4 = *(const float4*)&Ss[k*36 + vv];
                ull s01 = pk2(s4.x, s4.y), s23 = pk2(s4.z, s4.w);
                float4 wq = *(const float4*)&wqb[k*64 + cp2*4];
                ull wx = pk2(wq.x, wq.x);
                ffma2(ua0, wx, s01); ffma2(ua1, wx, s23);
                ull wy = pk2(wq.y, wq.y);
                ffma2(ua2, wy, s01); ffma2(ua3, wy, s23);
                ull qx = pk2(wq.z, wq.z);
                ffma2(oa0, qx, s01); ffma2(oa1, qx, s23);
                ull qy = pk2(wq.w, wq.w);
                ffma2(oa2, qy, s01); ffma2(oa3, qy, s23);
            }
        }
        // slices 2,3 publish partials
        if (slice >= 2) {
            float* red = sm + OFF_RED + (slice-2)*2048;
            float2 a0 = up2(ua0), a1 = up2(ua1), a2 = up2(ua2), a3 = up2(ua3);
            float2 b0 = up2(oa0), b1 = up2(oa1), b2 = up2(oa2), b3 = up2(oa3);
            *(float4*)&red[c0*32 + vv]           = make_float4(a0.x,a0.y,a1.x,a1.y);
            *(float4*)&red[(c0+1)*32 + vv]       = make_float4(a2.x,a2.y,a3.x,a3.y);
            *(float4*)&red[1024 + c0*32 + vv]    = make_float4(b0.x,b0.y,b1.x,b1.y);
            *(float4*)&red[1024 + (c0+1)*32 + vv]= make_float4(b2.x,b2.y,b3.x,b3.y);
        }
        __syncthreads();

        // ---- WQ(t+1) bulk now that phase-1 reads are done ----
        if (tid == 0 && t + 1 < NCH) {
            bulkcp(smb + OFF_WQ*4, g_wq + bhoff2 + (long)(t+1)*(2*CHELEM), 65536u, mbar);
        }

        // round A
        if (slice < 2) {
            const float* red = sm + OFF_RED + slice*2048;
            float4 ru0 = *(const float4*)&red[c0*32 + vv];
            float4 ru1 = *(const float4*)&red[(c0+1)*32 + vv];
            float4 ro0 = *(const float4*)&red[1024 + c0*32 + vv];
            float4 ro1 = *(const float4*)&red[1024 + (c0+1)*32 + vv];
            fadd2(ua0, pk2(ru0.x,ru0.y)); fadd2(ua1, pk2(ru0.z,ru0.w));
            fadd2(ua2, pk2(ru1.x,ru1.y)); fadd2(ua3, pk2(ru1.z,ru1.w));
            fadd2(oa0, pk2(ro0.x,ro0.y)); fadd2(oa1, pk2(ro0.z,ro0.w));
            fadd2(oa2, pk2(ro1.x,ro1.y)); fadd2(oa3, pk2(ro1.z,ro1.w));
        }
        if (slice == 1) {
            float* red = sm + OFF_RED + 2048;
            float2 a0 = up2(ua0), a1 = up2(ua1), a2 = up2(ua2), a3 = up2(ua3);
            float2 b0 = up2(oa0), b1 = up2(oa1), b2 = up2(oa2), b3 = up2(oa3);
            *(float4*)&red[c0*32 + vv]           = make_float4(a0.x,a0.y,a1.x,a1.y);
            *(float4*)&red[(c0+1)*32 + vv]       = make_float4(a2.x,a2.y,a3.x,a3.y);
            *(float4*)&red[1024 + c0*32 + vv]    = make_float4(b0.x,b0.y,b1.x,b1.y);
            *(float4*)&red[1024 + (c0+1)*32 + vv]= make_float4(b2.x,b2.y,b3.x,b3.y);
        }
        __syncthreads();

        // round B: slice 0 finalizes; computes us = u_raw - u, po = o
        if (slice == 0) {
            const float* red = sm + OFF_RED + 2048;
            float4 ru0 = *(const float4*)&red[c0*32 + vv];
            float4 ru1 = *(const float4*)&red[(c0+1)*32 + vv];
            float4 ro0 = *(const float4*)&red[1024 + c0*32 + vv];
            float4 ro1 = *(const float4*)&red[1024 + (c0+1)*32 + vv];
            fadd2(ua0, pk2(ru0.x,ru0.y)); fadd2(ua1, pk2(ru0.z,ru0.w));
            fadd2(ua2, pk2(ru1.x,ru1.y)); fadd2(ua3, pk2(ru1.z,ru1.w));
            fadd2(oa0, pk2(ro0.x,ro0.y)); fadd2(oa1, pk2(ro0.z,ro0.w));
            fadd2(oa2, pk2(ro1.x,ro1.y)); fadd2(oa3, pk2(ro1.z,ro1.w));

            const float* ub = sm + OFF_U + bsel*1024;
            float4 ur0 = *(const float4*)&ub[c0*32 + vv];
            float4 ur1 = *(const float4*)&ub[(c0+1)*32 + vv];
            float2 u0 = up2(ua0), u1 = up2(ua1), u2 = up2(ua2), u3 = up2(ua3);
            *(float4*)&us[c0*36 + vv] =
                make_float4(ur0.x-u0.x, ur0.y-u0.y, ur0.z-u1.x, ur0.w-u1.y);
            *(float4*)&us[(c0+1)*36 + vv] =
                make_float4(ur1.x-u2.x, ur1.y-u2.y, ur1.z-u3.x, ur1.w-u3.y);
            float2 o0 = up2(oa0), o1 = up2(oa1), o2 = up2(oa2), o3 = up2(oa3);
            *(float4*)&po[c0*36 + vv]     = make_float4(o0.x,o0.y,o1.x,o1.y);
            *(float4*)&po[(c0+1)*36 + vv] = make_float4(o2.x,o2.y,o3.x,o3.y);
        }
        __syncthreads();

        // ==== phase 2: o = po + attn_local . u  (triangular: d <= c) ====
        {
            const float* ab = sm + OFF_A + bsel*1024;
            float2 pv = *(const float2*)&po[c_p2*36 + v_p2];
            ull oacc = pk2(pv.x, pv.y);
            #pragma unroll 4
            for (int d = 0; d <= c_p2; d++) {
                float2 u2 = *(const float2*)&us[d*36 + v_p2];
                float av = ab[c_p2*32 + d];
                ffma2(oacc, pk2(av, av), pk2(u2.x, u2.y));
            }
            float2 r = up2(oacc);
            *(float2*)(outp + ((long)bh*LSEQ + (long)t*CC + c_p2)*DV + v0 + v_p2) = r;
        }

        // ==== phase 3: S = gm*S + kn^T . u ====
        {
            const float* kb = sm + OFF_K + bsel*8192;
            ull acc0=0,acc1=0,acc2=0,acc3=0,acc4=0,acc5=0,acc6=0,acc7=0;
            #pragma unroll 4
            for (int c = 0; c < 32; c++) {
                float4 kv4 = *(const float4*)&kb[c*256 + kx3];
                float4 u4  = *(const float4*)&us[c*36 + vv3];
                ull u01 = pk2(u4.x, u4.y), u23 = pk2(u4.z, u4.w);
                ull p0 = pk2(kv4.x, kv4.x); ffma2(acc0, p0, u01); ffma2(acc1, p0, u23);
                ull p1 = pk2(kv4.y, kv4.y); ffma2(acc2, p1, u01); ffma2(acc3, p1, u23);
                ull p2 = pk2(kv4.z, kv4.z); ffma2(acc4, p2, u01); ffma2(acc5, p2, u23);
                ull p3 = pk2(kv4.w, kv4.w); ffma2(acc6, p3, u01); ffma2(acc7, p3, u23);
            }
            const float gm = g_gm[bh*NCH + t];
            const ull gmp = pk2(gm, gm);
            const bool last = (t == NCH-1);
            float* sfp = sFinal + (long)bh*DK*DV;
            #pragma unroll
            for (int r = 0; r < 4; r++) {
                const int row = kx3 + r;
                ulonglong2 so = *(const ulonglong2*)&Ss[row*36 + vv3];
                ull n0, n1;
                switch (r) {
                    case 0: n0 = acc0; n1 = acc1; break;
                    case 1: n0 = acc2; n1 = acc3; break;
                    case 2: n0 = acc4; n1 = acc5; break;
                    default: n0 = acc6; n1 = acc7; break;
                }
                ffma2(n0, so.x, gmp);
                ffma2(n1, so.y, gmp);
                ulonglong2 sn; sn.x = n0; sn.y = n1;
                *(ulonglong2*)&Ss[row*36 + vv3] = sn;
                if (last) *(ulonglong2*)&sfp[(long)row*DV + v0 + vv3] = sn;
            }
        }
        // loop-top barrier orders phase-3 S writes vs next phase 1
    }
}

// ================= launch =================
extern "C" void kernel_launch(void* const* d_in, const int* in_sizes, int n_in,
                              void* d_out, int out_size) {
    const float* q     = (const float*)d_in[0];
    const float* k     = (const float*)d_in[1];
    const float* v     = (const float*)d_in[2];
    const float* beta  = (const float*)d_in[3];
    const float* gamma = (const float*)d_in[4];
    float* outp = (float*)d_out;
    float* sfin = outp + (long)BHn*LSEQ*DV;   // S appended after out

    cudaFuncSetAttribute(pre_kernel,  cudaFuncAttributeMaxDynamicSharedMemorySize,
                         PRE_SMEM_FLOATS*4);
    cudaFuncSetAttribute(scan_kernel, cudaFuncAttributeMaxDynamicSharedMemorySize,
                         SCAN_SMEM_FLOATS*4);
    (void)in_sizes; (void)n_in; (void)out_size;

    pre_kernel<<<BHn*NCH, 256, PRE_SMEM_FLOATS*4>>>(q, k, v, beta, gamma);
    scan_kernel<<<dim3(8, BHn), 512, SCAN_SMEM_FLOATS*4>>>(outp, sfin);
}